// round 13
// baseline (speedup 1.0000x reference)
#include <cuda_runtime.h>
#include <cuda_bf16.h>
#include <math.h>
#include <stdint.h>

// ---------------------------------------------------------------------------
// Problem constants
// ---------------------------------------------------------------------------
constexpr int BATCH = 8;
constexpr int DIM   = 384;
constexpr int NH    = 8;
constexpr int CH    = 48;
constexpr int HWD   = 16384;  // 128*128
constexpr int C3    = 1152;
constexpr int TOPKN = 7;

// split-precision GEMM constants (12 physical chunks of 32 real-k; 3 passes each)
constexpr int KC     = 32;            // real-k per physical chunk
constexpr int NCHUNK = DIM / KC;      // 12
constexpr int BM     = 128;
constexpr int BN     = 128;
constexpr int ATILE  = BM * 128;      // A: 128 rows x [hi 64B | lo 64B]
constexpr int BTILE  = KC * 512;      // B: 32 k-rows x [hi 256B | lo 256B]
constexpr int STAGE  = ATILE + BTILE; // 32 KB
constexpr int NSTAGE = 3;
constexpr int GEMM_SMEM = NSTAGE * STAGE;   // 96 KB

constexpr int GCH = 32;        // gram chunks

// dwconv strips
constexpr int SROWS = 32;
constexpr int NSTRIP = 128 / SROWS;       // 4
constexpr int SPITCH = 136;

// ---------------------------------------------------------------------------
// Scratch (device globals)
// ---------------------------------------------------------------------------
__device__ float g_qkv1[(size_t)BATCH * C3 * HWD];
__device__ float g_qkv2[(size_t)BATCH * C3 * HWD];   // only q,k region used
__device__ float g_ssp[BATCH * 768 * NSTRIP];
__device__ float g_inv[BATCH * 768];
__device__ float g_gpart[(size_t)GCH * BATCH * NH * CH * CH];
__device__ float g_attn[BATCH * NH * CH * CH];
__device__ __nv_bfloat16 g_A1hi[(size_t)C3 * DIM];
__device__ __nv_bfloat16 g_A1lo[(size_t)C3 * DIM];
__device__ __nv_bfloat16 g_xhi[(size_t)BATCH * DIM * HWD];
__device__ __nv_bfloat16 g_xlo[(size_t)BATCH * DIM * HWD];
__device__ __nv_bfloat16 g_vhi[(size_t)BATCH * DIM * HWD];
__device__ __nv_bfloat16 g_vlo[(size_t)BATCH * DIM * HWD];
__device__ __nv_bfloat16 g_Wbh[(size_t)BATCH * DIM * DIM];
__device__ __nv_bfloat16 g_Wbl[(size_t)BATCH * DIM * DIM];

// ---------------------------------------------------------------------------
// sm_80-portable PTX helpers
// ---------------------------------------------------------------------------
__device__ __forceinline__ uint32_t smem_u32(const void* p) {
    uint32_t a;
    asm("{ .reg .u64 t; cvta.to.shared.u64 t, %1; cvt.u32.u64 %0, t; }" : "=r"(a) : "l"(p));
    return a;
}

__device__ __forceinline__ void cp16(uint32_t saddr, const void* gaddr) {
    asm volatile("cp.async.cg.shared.global [%0], [%1], 16;" :: "r"(saddr), "l"(gaddr));
}
#define CP_COMMIT() asm volatile("cp.async.commit_group;" ::: "memory")

__device__ __forceinline__ void ldmx4(uint32_t* r, uint32_t addr) {
    asm volatile("ldmatrix.sync.aligned.m8n8.x4.shared.b16 {%0,%1,%2,%3}, [%4];"
                 : "=r"(r[0]), "=r"(r[1]), "=r"(r[2]), "=r"(r[3]) : "r"(addr));
}

__device__ __forceinline__ void ldmx4t(uint32_t* r, uint32_t addr) {
    asm volatile("ldmatrix.sync.aligned.m8n8.x4.trans.shared.b16 {%0,%1,%2,%3}, [%4];"
                 : "=r"(r[0]), "=r"(r[1]), "=r"(r[2]), "=r"(r[3]) : "r"(addr));
}

__device__ __forceinline__ void mma16816(float* c, const uint32_t* a, const uint32_t* b) {
    asm volatile(
        "mma.sync.aligned.m16n8k16.row.col.f32.bf16.bf16.f32 "
        "{%0,%1,%2,%3}, {%4,%5,%6,%7}, {%8,%9}, {%0,%1,%2,%3};"
        : "+f"(c[0]), "+f"(c[1]), "+f"(c[2]), "+f"(c[3])
        : "r"(a[0]), "r"(a[1]), "r"(a[2]), "r"(a[3]), "r"(b[0]), "r"(b[1]));
}

// ---------------------------------------------------------------------------
// Split-precision bf16 tensor-core GEMM, de-duplicated loads:
//   C = A_hi*B_hi + A_hi*B_lo + A_lo*B_hi     (fp32 accum)
// A planes [m][384] K-major; B planes [384][HWD] K-major.
// Stage: A rows 128x[hi64B|lo64B] (XOR-8 swizzle over 8 units/row),
//        B rows 32x[hi256B|lo256B] (XOR-8 swizzle per 16-unit half).
// ---------------------------------------------------------------------------
__global__ void __launch_bounds__(256, 2)
gemm_split(const __nv_bfloat16* __restrict__ Ahi,
           const __nv_bfloat16* __restrict__ Alo, long aBatchStride,
           const __nv_bfloat16* __restrict__ Bhi,
           const __nv_bfloat16* __restrict__ Blo,
           float* __restrict__ C, long cBatchStride)
{
    extern __shared__ char sm[];
    const uint32_t smBase = smem_u32(sm);

    const int tid = threadIdx.x;
    const int wid = tid >> 5, l = tid & 31;
    const int wm = wid >> 2, wn = wid & 3;
    const int bm0 = blockIdx.x * BM;
    const int bn0 = blockIdx.y * BN;
    const int bz  = blockIdx.z;

    const __nv_bfloat16* Abh = Ahi + (long)bz * aBatchStride + (long)bm0 * DIM;
    const __nv_bfloat16* Abl = Alo + (long)bz * aBatchStride + (long)bm0 * DIM;
    const __nv_bfloat16* Bhb = Bhi + (long)bz * DIM * HWD;
    const __nv_bfloat16* Blb = Blo + (long)bz * DIM * HWD;
    float* Cb = C + (long)bz * cBatchStride + (long)bm0 * HWD + bn0;

    // A loader: r = tid>>1 (0..127), half = tid&1, 4 units of 16B each
    const int a_r = tid >> 1, a_half = tid & 1;
    // B loader: row = tid>>3 (0..31), rem = tid&7 -> half = rem>>2, u0 = (rem&3)*4
    const int b_r = tid >> 3, b_half = (tid & 7) >> 2, b_u0 = (tid & 3) * 4;

    auto load_chunk = [&](int c, int s) {
        const uint32_t sA = smBase + s * STAGE;
        const uint32_t sB = sA + ATILE;
        {
            const __nv_bfloat16* src = (a_half ? Abl : Abh) + (long)a_r * DIM + c * KC;
            uint32_t base = sA + a_r * 128;
#pragma unroll
            for (int i = 0; i < 4; i++) {
                int u = a_half * 4 + i;
                cp16(base + ((u ^ (a_r & 7)) * 16), src + i * 8);
            }
        }
        {
            const __nv_bfloat16* src = (b_half ? Blb : Bhb)
                + (long)(c * KC + b_r) * HWD + bn0 + b_u0 * 8;
            uint32_t base = sB + b_r * 512 + b_half * 256;
#pragma unroll
            for (int i = 0; i < 4; i++) {
                int u = b_u0 + i;
                cp16(base + ((u ^ (b_r & 7)) * 16), src + i * 8);
            }
        }
        CP_COMMIT();
    };

    float acc[4][4][4] = {};

    const int l7 = l & 7;
    const int a_x = l >> 4;                       // k 8-half within 16
    int arow[4];
#pragma unroll
    for (int mi = 0; mi < 4; mi++)
        arow[mi] = (wm * 64 + mi * 16 + (l & 15)) * 128;
    const int b_row_l = l & 15;
    const int b_u_l   = wn * 4 + (l >> 4);

    load_chunk(0, 0);
    load_chunk(1, 1);

    for (int pc = 0; pc < NCHUNK; pc++) {
        if (pc + 2 < NCHUNK) {
            asm volatile("cp.async.wait_group 1;" ::: "memory");
        } else {
            asm volatile("cp.async.wait_group 0;" ::: "memory");
        }
        __syncthreads();
        if (pc + 2 < NCHUNK) load_chunk(pc + 2, (pc + 2) % NSTAGE);

        const int s = pc % NSTAGE;
        const uint32_t sA = smBase + s * STAGE;
        const uint32_t sB = sA + ATILE;

#pragma unroll
        for (int kk = 0; kk < 2; kk++) {
            uint32_t af[4][4], bf[4][2];
            const int brow = kk * 16 + b_row_l;
            const uint32_t brbase = sB + brow * 512;
            const int br7 = brow & 7;

            // ---- pass 1: A_hi x B_hi ----
#pragma unroll
            for (int mi = 0; mi < 4; mi++) {
                uint32_t u = (uint32_t)((kk * 2 + a_x) ^ l7);
                ldmx4(af[mi], sA + arow[mi] + u * 16);
            }
#pragma unroll
            for (int g = 0; g < 2; g++) {
                uint32_t t4[4];
                int u = b_u_l + g * 2;
                ldmx4t(t4, brbase + ((u ^ br7) * 16));
                bf[2 * g][0] = t4[0]; bf[2 * g][1] = t4[1];
                bf[2 * g + 1][0] = t4[2]; bf[2 * g + 1][1] = t4[3];
            }
#pragma unroll
            for (int mi = 0; mi < 4; mi++)
#pragma unroll
                for (int ni = 0; ni < 4; ni++)
                    mma16816(acc[mi][ni], af[mi], bf[ni]);

            // ---- pass 2: A_hi x B_lo (reuse af) ----
#pragma unroll
            for (int g = 0; g < 2; g++) {
                uint32_t t4[4];
                int u = b_u_l + g * 2;
                ldmx4t(t4, brbase + 256 + ((u ^ br7) * 16));
                bf[2 * g][0] = t4[0]; bf[2 * g][1] = t4[1];
                bf[2 * g + 1][0] = t4[2]; bf[2 * g + 1][1] = t4[3];
            }
#pragma unroll
            for (int mi = 0; mi < 4; mi++)
#pragma unroll
                for (int ni = 0; ni < 4; ni++)
                    mma16816(acc[mi][ni], af[mi], bf[ni]);

            // ---- pass 3: A_lo x B_hi (reload af lo, bf hi) ----
#pragma unroll
            for (int mi = 0; mi < 4; mi++) {
                uint32_t u = (uint32_t)((4 + kk * 2 + a_x) ^ l7);
                ldmx4(af[mi], sA + arow[mi] + u * 16);
            }
#pragma unroll
            for (int g = 0; g < 2; g++) {
                uint32_t t4[4];
                int u = b_u_l + g * 2;
                ldmx4t(t4, brbase + ((u ^ br7) * 16));
                bf[2 * g][0] = t4[0]; bf[2 * g][1] = t4[1];
                bf[2 * g + 1][0] = t4[2]; bf[2 * g + 1][1] = t4[3];
            }
#pragma unroll
            for (int mi = 0; mi < 4; mi++)
#pragma unroll
                for (int ni = 0; ni < 4; ni++)
                    mma16816(acc[mi][ni], af[mi], bf[ni]);
        }
        __syncthreads();
    }

    const int crow = l >> 2, ccol = (l & 3) * 2;
#pragma unroll
    for (int mi = 0; mi < 4; mi++) {
#pragma unroll
        for (int ni = 0; ni < 4; ni++) {
            float* p = Cb + (long)(wm * 64 + mi * 16 + crow) * HWD + wn * 32 + ni * 8 + ccol;
            *(float2*)p = make_float2(acc[mi][ni][0], acc[mi][ni][1]);
            *(float2*)(p + 8L * HWD) = make_float2(acc[mi][ni][2], acc[mi][ni][3]);
        }
    }
}

// ---------------------------------------------------------------------------
// Split qkv_w -> hi/lo planes [1152][384]
// ---------------------------------------------------------------------------
__global__ void split_w(const float* __restrict__ w,
                        __nv_bfloat16* __restrict__ ohi, __nv_bfloat16* __restrict__ olo)
{
    int idx = blockIdx.x * 256 + threadIdx.x;
    if (idx >= C3 * DIM) return;
    float v = w[idx];
    __nv_bfloat16 hi = __float2bfloat16(v);
    ohi[idx] = hi;
    olo[idx] = __float2bfloat16(v - __bfloat162float(hi));
}

// ---------------------------------------------------------------------------
// split_c: fp32 [b][384][HWD] -> hi/lo bf16 planes, same layout
// ---------------------------------------------------------------------------
__global__ void __launch_bounds__(256)
split_c(const float* __restrict__ src, __nv_bfloat16* __restrict__ hi,
        __nv_bfloat16* __restrict__ lo)
{
    long i4 = (long)blockIdx.x * 256 + threadIdx.x;   // float4 index
    float4 v = ((const float4*)src)[i4];
    __nv_bfloat16 hx = __float2bfloat16(v.x);
    __nv_bfloat16 hy = __float2bfloat16(v.y);
    __nv_bfloat16 hz = __float2bfloat16(v.z);
    __nv_bfloat16 hw = __float2bfloat16(v.w);
    __nv_bfloat162 h01, h23, l01, l23;
    h01.x = hx; h01.y = hy; h23.x = hz; h23.y = hw;
    l01.x = __float2bfloat16(v.x - __bfloat162float(hx));
    l01.y = __float2bfloat16(v.y - __bfloat162float(hy));
    l23.x = __float2bfloat16(v.z - __bfloat162float(hz));
    l23.y = __float2bfloat16(v.w - __bfloat162float(hw));
    ((__nv_bfloat162*)hi)[i4 * 2]     = h01;
    ((__nv_bfloat162*)hi)[i4 * 2 + 1] = h23;
    ((__nv_bfloat162*)lo)[i4 * 2]     = l01;
    ((__nv_bfloat162*)lo)[i4 * 2 + 1] = l23;
}

// ---------------------------------------------------------------------------
// Depthwise 3x3: q/k -> fp32 + norms, v -> bf16 hi/lo planes (unchanged)
// ---------------------------------------------------------------------------
__global__ void __launch_bounds__(256)
dwconv3(const float* __restrict__ in, const float* __restrict__ w,
        float* __restrict__ out, float* __restrict__ ssp,
        __nv_bfloat16* __restrict__ vhi, __nv_bfloat16* __restrict__ vlo)
{
    __shared__ float pl[(SROWS + 2) * SPITCH];
    __shared__ float red[256];

    const int strip = blockIdx.x & (NSTRIP - 1);
    const int c = (blockIdx.x >> 2) % C3;
    const int b = blockIdx.x / (NSTRIP * C3);
    const int tid = threadIdx.x;

#pragma unroll
    for (int i = tid; i < (SROWS + 2) * SPITCH; i += 256)
        pl[i] = 0.f;
    __syncthreads();

    const int r0 = strip * SROWS;
    const float* ip = in + ((long)b * C3 + c) * HWD;

    {
        const int rlo = (strip == 0) ? 1 : 0;
        const int rhi = (strip == NSTRIP - 1) ? SROWS : SROWS + 1;
        const int njobs = (rhi - rlo + 1) * 32;
        for (int i = tid; i < njobs; i += 256) {
            int lr = rlo + (i >> 5);
            int x4 = (i & 31) * 4;
            *(float4*)&pl[lr * SPITCH + 4 + x4] =
                *(const float4*)&ip[(long)(r0 - 1 + lr) * 128 + x4];
        }
    }

    const float* wp = w + c * 9;
    float w0 = wp[0], w1 = wp[1], w2 = wp[2];
    float w3 = wp[3], w4 = wp[4], w5 = wp[5];
    float w6 = wp[6], w7 = wp[7], w8 = wp[8];
    __syncthreads();

    const int tx = tid & 31, ty = tid >> 5;
    const int x4 = tx * 4;
    const int h0 = ty * 4;

    float4 Ar[3], Br[3], Cr[3];
    auto loadrow = [&](int srow, int slot) {
        int idx = srow * SPITCH + 4 + x4;
        Ar[slot] = *(float4*)&pl[idx - 4];
        Br[slot] = *(float4*)&pl[idx];
        Cr[slot] = *(float4*)&pl[idx + 4];
    };
    loadrow(h0 + 0, 0);
    loadrow(h0 + 1, 1);
    loadrow(h0 + 2, 2);

    const bool isV = (c >= 768);
    float4* op4 = (float4*)(out + ((long)b * C3 + c) * HWD + (long)r0 * 128);
    __nv_bfloat162* vh2 = nullptr;
    __nv_bfloat162* vl2 = nullptr;
    if (isV) {
        long off = ((long)b * DIM + (c - 768)) * HWD + (long)r0 * 128;
        vh2 = (__nv_bfloat162*)(vhi + off);
        vl2 = (__nv_bfloat162*)(vlo + off);
    }
    float ss = 0.f;

#pragma unroll
    for (int i = 0; i < 4; i++) {
        const int s0 = i % 3, s1 = (i + 1) % 3, s2 = (i + 2) % 3;
        float4 s;
        s.x = w0 * Ar[s0].w + w1 * Br[s0].x + w2 * Br[s0].y
            + w3 * Ar[s1].w + w4 * Br[s1].x + w5 * Br[s1].y
            + w6 * Ar[s2].w + w7 * Br[s2].x + w8 * Br[s2].y;
        s.y = w0 * Br[s0].x + w1 * Br[s0].y + w2 * Br[s0].z
            + w3 * Br[s1].x + w4 * Br[s1].y + w5 * Br[s1].z
            + w6 * Br[s2].x + w7 * Br[s2].y + w8 * Br[s2].z;
        s.z = w0 * Br[s0].y + w1 * Br[s0].z + w2 * Br[s0].w
            + w3 * Br[s1].y + w4 * Br[s1].z + w5 * Br[s1].w
            + w6 * Br[s2].y + w7 * Br[s2].z + w8 * Br[s2].w;
        s.w = w0 * Br[s0].z + w1 * Br[s0].w + w2 * Cr[s0].x
            + w3 * Br[s1].z + w4 * Br[s1].w + w5 * Cr[s1].x
            + w6 * Br[s2].z + w7 * Br[s2].w + w8 * Cr[s2].x;
        if (isV) {
            int e2 = (h0 + i) * 64 + tx * 2;
            __nv_bfloat16 hx = __float2bfloat16(s.x);
            __nv_bfloat16 hy = __float2bfloat16(s.y);
            __nv_bfloat16 hz = __float2bfloat16(s.z);
            __nv_bfloat16 hw = __float2bfloat16(s.w);
            __nv_bfloat162 h01, h23, l01, l23;
            h01.x = hx; h01.y = hy; h23.x = hz; h23.y = hw;
            l01.x = __float2bfloat16(s.x - __bfloat162float(hx));
            l01.y = __float2bfloat16(s.y - __bfloat162float(hy));
            l23.x = __float2bfloat16(s.z - __bfloat162float(hz));
            l23.y = __float2bfloat16(s.w - __bfloat162float(hw));
            vh2[e2] = h01; vh2[e2 + 1] = h23;
            vl2[e2] = l01; vl2[e2 + 1] = l23;
        } else {
            op4[(h0 + i) * 32 + tx] = s;
            ss += s.x * s.x + s.y * s.y + s.z * s.z + s.w * s.w;
        }
        if (i < 3) loadrow(h0 + 3 + i, s0);
    }

    if (c < 768) {
        red[tid] = ss;
        __syncthreads();
        for (int st = 128; st > 0; st >>= 1) {
            if (tid < st) red[tid] += red[tid + st];
            __syncthreads();
        }
        if (tid == 0)
            ssp[(b * 768 + c) * NSTRIP + strip] = red[0];
    }
}

// finalize inv norms from strip partials
__global__ void norm_fin(const float* __restrict__ ssp, float* __restrict__ inv)
{
    int i = blockIdx.x * 256 + threadIdx.x;
    if (i >= BATCH * 768) return;
    float s = 0.f;
#pragma unroll
    for (int j = 0; j < NSTRIP; j++) s += ssp[i * NSTRIP + j];
    inv[i] = 1.f / fmaxf(sqrtf(s), 1e-12f);
}

// ---------------------------------------------------------------------------
// Gram partial (unchanged)
// ---------------------------------------------------------------------------
__global__ void __launch_bounds__(256)
gram_partial(const float* __restrict__ qkv2, float* __restrict__ gpart)
{
    const int chunk = blockIdx.x;
    const int bh = blockIdx.y;
    const int b = bh >> 3, h = bh & 7;
    const float* qb = qkv2 + ((long)b * C3 + h * CH) * HWD;
    const float* kb = qb + (long)DIM * HWD;

    __shared__ float qs[64][49], ks[64][49];
    const int tid = threadIdx.x;
    const int tx = tid & 15, ty = tid >> 4;
    float acc[3][3] = {};

    const int n0 = chunk * 512;
    for (int slab = 0; slab < 8; slab++) {
        const int base = n0 + slab * 64;
        __syncthreads();
#pragma unroll
        for (int j = 0; j < 3; j++) {
            int id = tid + j * 256;
            int rid = id >> 4, c4 = id & 15;
            float4 v = *(const float4*)(qb + (long)rid * HWD + base + c4 * 4);
            qs[c4 * 4 + 0][rid] = v.x; qs[c4 * 4 + 1][rid] = v.y;
            qs[c4 * 4 + 2][rid] = v.z; qs[c4 * 4 + 3][rid] = v.w;
            float4 u = *(const float4*)(kb + (long)rid * HWD + base + c4 * 4);
            ks[c4 * 4 + 0][rid] = u.x; ks[c4 * 4 + 1][rid] = u.y;
            ks[c4 * 4 + 2][rid] = u.z; ks[c4 * 4 + 3][rid] = u.w;
        }
        __syncthreads();
#pragma unroll 8
        for (int t = 0; t < 64; t++) {
            float qa[3], ka[3];
#pragma unroll
            for (int i = 0; i < 3; i++) qa[i] = qs[t][ty * 3 + i];
#pragma unroll
            for (int j = 0; j < 3; j++) ka[j] = ks[t][tx * 3 + j];
#pragma unroll
            for (int i = 0; i < 3; i++)
#pragma unroll
                for (int j = 0; j < 3; j++)
                    acc[i][j] += qa[i] * ka[j];
        }
    }
    float* op = gpart + ((long)chunk * 64 + bh) * (CH * CH);
#pragma unroll
    for (int i = 0; i < 3; i++)
#pragma unroll
        for (int j = 0; j < 3; j++)
            op[(ty * 3 + i) * CH + tx * 3 + j] = acc[i][j];
}

__global__ void gram_scale(const float* __restrict__ gpart, const float* __restrict__ inv,
                           const float* __restrict__ temp, float* __restrict__ attn)
{
    int idx = blockIdx.x * 256 + threadIdx.x;
    if (idx >= 64 * CH * CH) return;
    int bh = idx / (CH * CH), r = idx % (CH * CH);
    int c = r / CH, d = r % CH;
    int b = bh >> 3, h = bh & 7;
    float s = 0.f;
#pragma unroll
    for (int ck = 0; ck < GCH; ck++) s += gpart[((long)ck * 64 + bh) * (CH * CH) + r];
    float iq = inv[b * 768 + h * CH + c];
    float ik = inv[b * 768 + 384 + h * CH + d];
    attn[idx] = s * iq * ik * temp[h];
}

__global__ void topk_softmax(float* __restrict__ attn)
{
    int row = blockIdx.x;
    float* p = attn + (long)row * CH;
    __shared__ float s[CH], e[CH];
    int i = threadIdx.x;
    if (i < CH) s[i] = p[i];
    __syncthreads();
    if (i < CH) {
        float v = s[i];
        int cnt = 0;
        float m = -1e30f;
#pragma unroll
        for (int j = 0; j < CH; j++) {
            cnt += (s[j] > v);
            m = fmaxf(m, s[j]);
        }
        e[i] = (cnt < TOPKN) ? expf(v - m) : 0.f;
    }
    __syncthreads();
    if (i < CH) {
        float sum = 0.f;
#pragma unroll
        for (int j = 0; j < CH; j++) sum += e[j];
        p[i] = e[i] / sum;
    }
}

// ---------------------------------------------------------------------------
// Fold proj_w @ blockdiag(attn) -> hi/lo planes [b][o][384]
// ---------------------------------------------------------------------------
__global__ void fold_proj(const float* __restrict__ projw, const float* __restrict__ attn,
                          __nv_bfloat16* __restrict__ Wbh, __nv_bfloat16* __restrict__ Wbl)
{
    int idx = blockIdx.x * 256 + threadIdx.x;
    if (idx >= BATCH * DIM * DIM) return;
    int b = idx / (DIM * DIM);
    int r = idx % (DIM * DIM);
    int o = r / DIM, dg = r % DIM;
    int h = dg / CH, d = dg % CH;
    const float* pw = projw + o * DIM + h * CH;
    const float* at = attn + ((long)(b * NH + h) * CH) * CH + d;
    float s = 0.f;
#pragma unroll
    for (int c = 0; c < CH; c++) s += pw[c] * at[c * CH];
    __nv_bfloat16 hi = __float2bfloat16(s);
    Wbh[idx] = hi;
    Wbl[idx] = __float2bfloat16(s - __bfloat162float(hi));
}

// ---------------------------------------------------------------------------
extern "C" void kernel_launch(void* const* d_in, const int* in_sizes, int n_in,
                              void* d_out, int out_size)
{
    const float* x      = (const float*)d_in[0];
    const float* qkv_w  = (const float*)d_in[1];
    const float* dw_w   = (const float*)d_in[2];
    const float* proj_w = (const float*)d_in[3];
    const float* temp   = (const float*)d_in[4];
    float* out = (float*)d_out;

    float *qkv1, *qkv2, *ssp, *inv, *gpart, *attn;
    __nv_bfloat16 *A1hi, *A1lo, *xhi, *xlo, *vhi, *vlo, *Wbh, *Wbl;
    cudaGetSymbolAddress((void**)&qkv1,  g_qkv1);
    cudaGetSymbolAddress((void**)&qkv2,  g_qkv2);
    cudaGetSymbolAddress((void**)&ssp,   g_ssp);
    cudaGetSymbolAddress((void**)&inv,   g_inv);
    cudaGetSymbolAddress((void**)&gpart, g_gpart);
    cudaGetSymbolAddress((void**)&attn,  g_attn);
    cudaGetSymbolAddress((void**)&A1hi,  g_A1hi);
    cudaGetSymbolAddress((void**)&A1lo,  g_A1lo);
    cudaGetSymbolAddress((void**)&xhi,   g_xhi);
    cudaGetSymbolAddress((void**)&xlo,   g_xlo);
    cudaGetSymbolAddress((void**)&vhi,   g_vhi);
    cudaGetSymbolAddress((void**)&vlo,   g_vlo);
    cudaGetSymbolAddress((void**)&Wbh,   g_Wbh);
    cudaGetSymbolAddress((void**)&Wbl,   g_Wbl);

    cudaFuncSetAttribute(gemm_split, cudaFuncAttributeMaxDynamicSharedMemorySize, GEMM_SMEM);

    // 0) operand prep
    split_w<<<(C3 * DIM + 255) / 256, 256>>>(qkv_w, A1hi, A1lo);
    split_c<<<(int)(((long)BATCH * DIM * HWD / 4) / 256), 256>>>(x, xhi, xlo);

    // 1) qkv = qkv_w @ x
    gemm_split<<<dim3(C3 / BM, HWD / BN, BATCH), 256, GEMM_SMEM>>>(
        A1hi, A1lo, 0L, xhi, xlo, qkv1, (long)C3 * HWD);

    // 2) depthwise 3x3: q/k -> fp32 + norms, v -> bf16 hi/lo planes
    dwconv3<<<BATCH * C3 * NSTRIP, 256>>>(qkv1, dw_w, qkv2, ssp, vhi, vlo);
    norm_fin<<<(BATCH * 768 + 255) / 256, 256>>>(ssp, inv);

    // 3) Gram + scale
    gram_partial<<<dim3(GCH, BATCH * NH), 256>>>(qkv2, gpart);
    gram_scale<<<(64 * CH * CH + 255) / 256, 256>>>(gpart, inv, temp, attn);

    // 4) top-7 + softmax
    topk_softmax<<<BATCH * NH * CH, 64>>>(attn);

    // 5) fold proj @ blockdiag(attn)
    fold_proj<<<(BATCH * DIM * DIM + 255) / 256, 256>>>(proj_w, attn, Wbh, Wbl);

    // 6) out = Wb @ v
    gemm_split<<<dim3(DIM / BM, HWD / BN, BATCH), 256, GEMM_SMEM>>>(
        Wbh, Wbl, (long)DIM * DIM, vhi, vlo, out, (long)DIM * HWD);
}

// round 14
// speedup vs baseline: 1.2024x; 1.2024x over previous
#include <cuda_runtime.h>
#include <cuda_bf16.h>
#include <math.h>
#include <stdint.h>

// ---------------------------------------------------------------------------
// Problem constants
// ---------------------------------------------------------------------------
constexpr int BATCH = 8;
constexpr int DIM   = 384;
constexpr int NH    = 8;
constexpr int CH    = 48;
constexpr int HWD   = 16384;  // 128*128
constexpr int C3    = 1152;
constexpr int TOPKN = 7;

// split-precision GEMM constants (R12 structure)
constexpr int KP     = 1152;     // K' = 3*384 (hi*hi, lo*hi, hi*lo)
constexpr int KC     = 64;
constexpr int NCHUNK = KP / KC;  // 18
constexpr int BM     = 128;
constexpr int BN     = 128;
constexpr int ATILE  = BM * 128;       // A: 128 rows x 128B (k-contig rows)
constexpr int BTILE  = KC * 256;       // B: 64 k-rows x 256B (n-contig rows)
constexpr int STAGE  = ATILE + BTILE;  // 32 KB
constexpr int NSTAGE = 3;
constexpr int GEMM_SMEM = NSTAGE * STAGE;   // 96 KB

constexpr int GCH = 32;        // gram chunks

// dwconv strips
constexpr int SROWS = 32;
constexpr int NSTRIP = 128 / SROWS;       // 4
constexpr int SPITCH = 136;

// chunk interleave: duplicated B_hi tiles consumed back-to-back
__device__ __forceinline__ int chunk_order(int pc) {
    return (pc < 12) ? ((pc >> 1) + (pc & 1) * 6) : pc;
}

// ---------------------------------------------------------------------------
// Scratch (device globals)
// ---------------------------------------------------------------------------
__device__ float g_qkv1[(size_t)BATCH * C3 * HWD];
__device__ float g_qkv2[(size_t)BATCH * C3 * HWD];   // only q,k region used
__device__ float g_ssp[BATCH * 768 * NSTRIP];
__device__ float g_inv[BATCH * 768];
__device__ float g_gpart[(size_t)GCH * BATCH * NH * CH * CH];
__device__ float g_attn[BATCH * NH * CH * CH];
__device__ __nv_bfloat16 g_A1[(size_t)C3 * KP];
__device__ __nv_bfloat16 g_xhi[(size_t)BATCH * DIM * HWD];
__device__ __nv_bfloat16 g_xlo[(size_t)BATCH * DIM * HWD];
__device__ __nv_bfloat16 g_vhi[(size_t)BATCH * DIM * HWD];
__device__ __nv_bfloat16 g_vlo[(size_t)BATCH * DIM * HWD];
__device__ __nv_bfloat16 g_Wbs[(size_t)BATCH * DIM * KP];

// ---------------------------------------------------------------------------
// sm_80-portable PTX helpers
// ---------------------------------------------------------------------------
__device__ __forceinline__ uint32_t smem_u32(const void* p) {
    uint32_t a;
    asm("{ .reg .u64 t; cvta.to.shared.u64 t, %1; cvt.u32.u64 %0, t; }" : "=r"(a) : "l"(p));
    return a;
}

__device__ __forceinline__ void cp16(uint32_t saddr, const void* gaddr) {
    asm volatile("cp.async.cg.shared.global [%0], [%1], 16;" :: "r"(saddr), "l"(gaddr));
}
#define CP_COMMIT() asm volatile("cp.async.commit_group;" ::: "memory")

__device__ __forceinline__ void ldmx4(uint32_t* r, uint32_t addr) {
    asm volatile("ldmatrix.sync.aligned.m8n8.x4.shared.b16 {%0,%1,%2,%3}, [%4];"
                 : "=r"(r[0]), "=r"(r[1]), "=r"(r[2]), "=r"(r[3]) : "r"(addr));
}

__device__ __forceinline__ void ldmx4t(uint32_t* r, uint32_t addr) {
    asm volatile("ldmatrix.sync.aligned.m8n8.x4.trans.shared.b16 {%0,%1,%2,%3}, [%4];"
                 : "=r"(r[0]), "=r"(r[1]), "=r"(r[2]), "=r"(r[3]) : "r"(addr));
}

__device__ __forceinline__ void mma16816(float* c, const uint32_t* a, const uint32_t* b) {
    asm volatile(
        "mma.sync.aligned.m16n8k16.row.col.f32.bf16.bf16.f32 "
        "{%0,%1,%2,%3}, {%4,%5,%6,%7}, {%8,%9}, {%0,%1,%2,%3};"
        : "+f"(c[0]), "+f"(c[1]), "+f"(c[2]), "+f"(c[3])
        : "r"(a[0]), "r"(a[1]), "r"(a[2]), "r"(a[3]), "r"(b[0]), "r"(b[1]));
}

// ---------------------------------------------------------------------------
// Split-precision bf16 tensor-core GEMM (R12 structure + chunk interleave).
//   C[bz][m][n] = sum_{k'} A'[m][k'] * B'[n][seg(k')]
// A' rows [hi|lo|hi] (KP cols, K-major).
// B source K-major planes Bhi/Blo [bz][384][HWD] bf16.
// Chunk c: seg = (c<12 ? hi : lo), k0 = (c%6)*64.
// ---------------------------------------------------------------------------
__global__ void __launch_bounds__(256, 2)
gemm_split(const __nv_bfloat16* __restrict__ A, long aBatchStride,
           const __nv_bfloat16* __restrict__ Bhi,
           const __nv_bfloat16* __restrict__ Blo,
           float* __restrict__ C, long cBatchStride)
{
    extern __shared__ char sm[];
    const uint32_t smBase = smem_u32(sm);

    const int tid = threadIdx.x;
    const int wid = tid >> 5, l = tid & 31;
    const int wm = wid >> 2, wn = wid & 3;
    const int bm0 = blockIdx.x * BM;
    const int bn0 = blockIdx.y * BN;
    const int bz  = blockIdx.z;

    const __nv_bfloat16* Ab  = A + (long)bz * aBatchStride + (long)bm0 * KP;
    const __nv_bfloat16* Bhb = Bhi + (long)bz * DIM * HWD;
    const __nv_bfloat16* Blb = Blo + (long)bz * DIM * HWD;
    float* Cb = C + (long)bz * cBatchStride + (long)bm0 * HWD + bn0;

    const int ldr = tid >> 3, ldq = tid & 7;     // A loader mapping
    const int bro = tid >> 2, bu0 = tid & 3;     // B loader mapping

    auto load_chunk = [&](int c, int s) {
        const uint32_t sA = smBase + s * STAGE;
        const uint32_t sB = sA + ATILE;
        const __nv_bfloat16* ac = Ab + c * KC;
#pragma unroll
        for (int i = 0; i < 4; i++) {
            int r = ldr + i * 32;
            int u = ldq ^ (r & 7);
            cp16(sA + r * 128 + u * 16, ac + (long)r * KP + ldq * 8);
        }
        const __nv_bfloat16* bsrc = (c < 12) ? Bhb : Blb;
        const int k0 = (c % 6) * KC;
        const __nv_bfloat16* brow = bsrc + (long)(k0 + bro) * HWD + bn0;
#pragma unroll
        for (int i = 0; i < 4; i++) {
            int u = bu0 + 4 * i;
            cp16(sB + bro * 256 + ((u ^ (bro & 7)) * 16), brow + u * 8);
        }
        CP_COMMIT();
    };

    float acc[4][4][4] = {};

    const int l7 = l & 7;
    const int a_x = l >> 4;
    int arow[4];
#pragma unroll
    for (int mi = 0; mi < 4; mi++)
        arow[mi] = (wm * 64 + mi * 16 + (l & 15)) * 128;

    const int b_row_l = l & 15;
    const int b_u_l   = wn * 4 + (l >> 4);

    load_chunk(chunk_order(0), 0);
    load_chunk(chunk_order(1), 1);

    for (int pc = 0; pc < NCHUNK; pc++) {
        if (pc + 2 < NCHUNK) {
            asm volatile("cp.async.wait_group 1;" ::: "memory");
        } else {
            asm volatile("cp.async.wait_group 0;" ::: "memory");
        }
        __syncthreads();
        if (pc + 2 < NCHUNK) load_chunk(chunk_order(pc + 2), (pc + 2) % NSTAGE);

        const int s = pc % NSTAGE;
        const uint32_t sA = smBase + s * STAGE;
        const uint32_t sB = sA + ATILE;

#pragma unroll
        for (int kk = 0; kk < 4; kk++) {
            uint32_t afr[4][4];
#pragma unroll
            for (int mi = 0; mi < 4; mi++) {
                uint32_t u = (uint32_t)((kk * 2 + a_x) ^ l7);
                ldmx4(afr[mi], sA + arow[mi] + u * 16);
            }
            uint32_t bfr[4][2];
#pragma unroll
            for (int g = 0; g < 2; g++) {
                uint32_t t4[4];
                int row = kk * 16 + b_row_l;
                int u = b_u_l + g * 2;
                ldmx4t(t4, sB + row * 256 + ((u ^ (row & 7)) * 16));
                bfr[2 * g][0] = t4[0]; bfr[2 * g][1] = t4[1];
                bfr[2 * g + 1][0] = t4[2]; bfr[2 * g + 1][1] = t4[3];
            }
#pragma unroll
            for (int mi = 0; mi < 4; mi++)
#pragma unroll
                for (int ni = 0; ni < 4; ni++)
                    mma16816(acc[mi][ni], afr[mi], bfr[ni]);
        }
        __syncthreads();
    }

    const int crow = l >> 2, ccol = (l & 3) * 2;
#pragma unroll
    for (int mi = 0; mi < 4; mi++) {
#pragma unroll
        for (int ni = 0; ni < 4; ni++) {
            float* p = Cb + (long)(wm * 64 + mi * 16 + crow) * HWD + wn * 32 + ni * 8 + ccol;
            *(float2*)p = make_float2(acc[mi][ni][0], acc[mi][ni][1]);
            *(float2*)(p + 8L * HWD) = make_float2(acc[mi][ni][2], acc[mi][ni][3]);
        }
    }
}

// ---------------------------------------------------------------------------
// Split qkv_w -> A' [1152][1152] bf16 = [hi | lo | hi]
// ---------------------------------------------------------------------------
__global__ void split_w(const float* __restrict__ w, __nv_bfloat16* __restrict__ o)
{
    int idx = blockIdx.x * 256 + threadIdx.x;
    if (idx >= C3 * DIM) return;
    int m = idx / DIM, k = idx % DIM;
    float v = w[idx];
    __nv_bfloat16 hi = __float2bfloat16(v);
    __nv_bfloat16 lo = __float2bfloat16(v - __bfloat162float(hi));
    o[(long)m * KP + k]       = hi;
    o[(long)m * KP + 384 + k] = lo;
    o[(long)m * KP + 768 + k] = hi;
}

// ---------------------------------------------------------------------------
// split_c: fp32 [b][384][HWD] -> hi/lo bf16 planes, same layout
// ---------------------------------------------------------------------------
__global__ void __launch_bounds__(256)
split_c(const float* __restrict__ src, __nv_bfloat16* __restrict__ hi,
        __nv_bfloat16* __restrict__ lo)
{
    long i4 = (long)blockIdx.x * 256 + threadIdx.x;   // float4 index
    float4 v = ((const float4*)src)[i4];
    __nv_bfloat16 hx = __float2bfloat16(v.x);
    __nv_bfloat16 hy = __float2bfloat16(v.y);
    __nv_bfloat16 hz = __float2bfloat16(v.z);
    __nv_bfloat16 hw = __float2bfloat16(v.w);
    __nv_bfloat162 h01, h23, l01, l23;
    h01.x = hx; h01.y = hy; h23.x = hz; h23.y = hw;
    l01.x = __float2bfloat16(v.x - __bfloat162float(hx));
    l01.y = __float2bfloat16(v.y - __bfloat162float(hy));
    l23.x = __float2bfloat16(v.z - __bfloat162float(hz));
    l23.y = __float2bfloat16(v.w - __bfloat162float(hw));
    ((__nv_bfloat162*)hi)[i4 * 2]     = h01;
    ((__nv_bfloat162*)hi)[i4 * 2 + 1] = h23;
    ((__nv_bfloat162*)lo)[i4 * 2]     = l01;
    ((__nv_bfloat162*)lo)[i4 * 2 + 1] = l23;
}

// ---------------------------------------------------------------------------
// Depthwise 3x3: q/k -> fp32 + norms, v -> bf16 hi/lo planes
// ---------------------------------------------------------------------------
__global__ void __launch_bounds__(256)
dwconv3(const float* __restrict__ in, const float* __restrict__ w,
        float* __restrict__ out, float* __restrict__ ssp,
        __nv_bfloat16* __restrict__ vhi, __nv_bfloat16* __restrict__ vlo)
{
    __shared__ float pl[(SROWS + 2) * SPITCH];
    __shared__ float red[256];

    const int strip = blockIdx.x & (NSTRIP - 1);
    const int c = (blockIdx.x >> 2) % C3;
    const int b = blockIdx.x / (NSTRIP * C3);
    const int tid = threadIdx.x;

#pragma unroll
    for (int i = tid; i < (SROWS + 2) * SPITCH; i += 256)
        pl[i] = 0.f;
    __syncthreads();

    const int r0 = strip * SROWS;
    const float* ip = in + ((long)b * C3 + c) * HWD;

    {
        const int rlo = (strip == 0) ? 1 : 0;
        const int rhi = (strip == NSTRIP - 1) ? SROWS : SROWS + 1;
        const int njobs = (rhi - rlo + 1) * 32;
        for (int i = tid; i < njobs; i += 256) {
            int lr = rlo + (i >> 5);
            int x4 = (i & 31) * 4;
            *(float4*)&pl[lr * SPITCH + 4 + x4] =
                *(const float4*)&ip[(long)(r0 - 1 + lr) * 128 + x4];
        }
    }

    const float* wp = w + c * 9;
    float w0 = wp[0], w1 = wp[1], w2 = wp[2];
    float w3 = wp[3], w4 = wp[4], w5 = wp[5];
    float w6 = wp[6], w7 = wp[7], w8 = wp[8];
    __syncthreads();

    const int tx = tid & 31, ty = tid >> 5;
    const int x4 = tx * 4;
    const int h0 = ty * 4;

    float4 Ar[3], Br[3], Cr[3];
    auto loadrow = [&](int srow, int slot) {
        int idx = srow * SPITCH + 4 + x4;
        Ar[slot] = *(float4*)&pl[idx - 4];
        Br[slot] = *(float4*)&pl[idx];
        Cr[slot] = *(float4*)&pl[idx + 4];
    };
    loadrow(h0 + 0, 0);
    loadrow(h0 + 1, 1);
    loadrow(h0 + 2, 2);

    const bool isV = (c >= 768);
    float4* op4 = (float4*)(out + ((long)b * C3 + c) * HWD + (long)r0 * 128);
    __nv_bfloat162* vh2 = nullptr;
    __nv_bfloat162* vl2 = nullptr;
    if (isV) {
        long off = ((long)b * DIM + (c - 768)) * HWD + (long)r0 * 128;
        vh2 = (__nv_bfloat162*)(vhi + off);
        vl2 = (__nv_bfloat162*)(vlo + off);
    }
    float ss = 0.f;

#pragma unroll
    for (int i = 0; i < 4; i++) {
        const int s0 = i % 3, s1 = (i + 1) % 3, s2 = (i + 2) % 3;
        float4 s;
        s.x = w0 * Ar[s0].w + w1 * Br[s0].x + w2 * Br[s0].y
            + w3 * Ar[s1].w + w4 * Br[s1].x + w5 * Br[s1].y
            + w6 * Ar[s2].w + w7 * Br[s2].x + w8 * Br[s2].y;
        s.y = w0 * Br[s0].x + w1 * Br[s0].y + w2 * Br[s0].z
            + w3 * Br[s1].x + w4 * Br[s1].y + w5 * Br[s1].z
            + w6 * Br[s2].x + w7 * Br[s2].y + w8 * Br[s2].z;
        s.z = w0 * Br[s0].y + w1 * Br[s0].z + w2 * Br[s0].w
            + w3 * Br[s1].y + w4 * Br[s1].z + w5 * Br[s1].w
            + w6 * Br[s2].y + w7 * Br[s2].z + w8 * Br[s2].w;
        s.w = w0 * Br[s0].z + w1 * Br[s0].w + w2 * Cr[s0].x
            + w3 * Br[s1].z + w4 * Br[s1].w + w5 * Cr[s1].x
            + w6 * Br[s2].z + w7 * Br[s2].w + w8 * Cr[s2].x;
        if (isV) {
            int e2 = (h0 + i) * 64 + tx * 2;
            __nv_bfloat16 hx = __float2bfloat16(s.x);
            __nv_bfloat16 hy = __float2bfloat16(s.y);
            __nv_bfloat16 hz = __float2bfloat16(s.z);
            __nv_bfloat16 hw = __float2bfloat16(s.w);
            __nv_bfloat162 h01, h23, l01, l23;
            h01.x = hx; h01.y = hy; h23.x = hz; h23.y = hw;
            l01.x = __float2bfloat16(s.x - __bfloat162float(hx));
            l01.y = __float2bfloat16(s.y - __bfloat162float(hy));
            l23.x = __float2bfloat16(s.z - __bfloat162float(hz));
            l23.y = __float2bfloat16(s.w - __bfloat162float(hw));
            vh2[e2] = h01; vh2[e2 + 1] = h23;
            vl2[e2] = l01; vl2[e2 + 1] = l23;
        } else {
            op4[(h0 + i) * 32 + tx] = s;
            ss += s.x * s.x + s.y * s.y + s.z * s.z + s.w * s.w;
        }
        if (i < 3) loadrow(h0 + 3 + i, s0);
    }

    if (c < 768) {
        red[tid] = ss;
        __syncthreads();
        for (int st = 128; st > 0; st >>= 1) {
            if (tid < st) red[tid] += red[tid + st];
            __syncthreads();
        }
        if (tid == 0)
            ssp[(b * 768 + c) * NSTRIP + strip] = red[0];
    }
}

// finalize inv norms from strip partials
__global__ void norm_fin(const float* __restrict__ ssp, float* __restrict__ inv)
{
    int i = blockIdx.x * 256 + threadIdx.x;
    if (i >= BATCH * 768) return;
    float s = 0.f;
#pragma unroll
    for (int j = 0; j < NSTRIP; j++) s += ssp[i * NSTRIP + j];
    inv[i] = 1.f / fmaxf(sqrtf(s), 1e-12f);
}

// ---------------------------------------------------------------------------
// Gram partial (unchanged)
// ---------------------------------------------------------------------------
__global__ void __launch_bounds__(256)
gram_partial(const float* __restrict__ qkv2, float* __restrict__ gpart)
{
    const int chunk = blockIdx.x;
    const int bh = blockIdx.y;
    const int b = bh >> 3, h = bh & 7;
    const float* qb = qkv2 + ((long)b * C3 + h * CH) * HWD;
    const float* kb = qb + (long)DIM * HWD;

    __shared__ float qs[64][49], ks[64][49];
    const int tid = threadIdx.x;
    const int tx = tid & 15, ty = tid >> 4;
    float acc[3][3] = {};

    const int n0 = chunk * 512;
    for (int slab = 0; slab < 8; slab++) {
        const int base = n0 + slab * 64;
        __syncthreads();
#pragma unroll
        for (int j = 0; j < 3; j++) {
            int id = tid + j * 256;
            int rid = id >> 4, c4 = id & 15;
            float4 v = *(const float4*)(qb + (long)rid * HWD + base + c4 * 4);
            qs[c4 * 4 + 0][rid] = v.x; qs[c4 * 4 + 1][rid] = v.y;
            qs[c4 * 4 + 2][rid] = v.z; qs[c4 * 4 + 3][rid] = v.w;
            float4 u = *(const float4*)(kb + (long)rid * HWD + base + c4 * 4);
            ks[c4 * 4 + 0][rid] = u.x; ks[c4 * 4 + 1][rid] = u.y;
            ks[c4 * 4 + 2][rid] = u.z; ks[c4 * 4 + 3][rid] = u.w;
        }
        __syncthreads();
#pragma unroll 8
        for (int t = 0; t < 64; t++) {
            float qa[3], ka[3];
#pragma unroll
            for (int i = 0; i < 3; i++) qa[i] = qs[t][ty * 3 + i];
#pragma unroll
            for (int j = 0; j < 3; j++) ka[j] = ks[t][tx * 3 + j];
#pragma unroll
            for (int i = 0; i < 3; i++)
#pragma unroll
                for (int j = 0; j < 3; j++)
                    acc[i][j] += qa[i] * ka[j];
        }
    }
    float* op = gpart + ((long)chunk * 64 + bh) * (CH * CH);
#pragma unroll
    for (int i = 0; i < 3; i++)
#pragma unroll
        for (int j = 0; j < 3; j++)
            op[(ty * 3 + i) * CH + tx * 3 + j] = acc[i][j];
}

// ---------------------------------------------------------------------------
// Fused: reduce partials + scale + top-7 masked softmax. One block per (b,h).
// ---------------------------------------------------------------------------
__global__ void __launch_bounds__(256)
attn_fuse(const float* __restrict__ gpart, const float* __restrict__ inv,
          const float* __restrict__ temp, float* __restrict__ attn)
{
    __shared__ float at[CH][CH + 1];
    __shared__ float eb[CH][CH + 1];
    __shared__ float rsum[CH];

    const int bh = blockIdx.x;
    const int b = bh >> 3, h = bh & 7;
    const int tid = threadIdx.x;
    const float tmp = temp[h];

    for (int e = tid; e < CH * CH; e += 256) {
        int c = e / CH, d = e % CH;
        float s = 0.f;
#pragma unroll
        for (int ck = 0; ck < GCH; ck++)
            s += gpart[((long)ck * 64 + bh) * (CH * CH) + e];
        at[c][d] = s * inv[b * 768 + h * CH + c] * inv[b * 768 + 384 + h * CH + d] * tmp;
    }
    __syncthreads();

    // top-7 + exp: 5 rows per wave (240 threads active)
    const int rr = tid / CH, cc = tid % CH;
#pragma unroll
    for (int wv = 0; wv < 10; wv++) {
        int r = wv * 5 + rr;
        if (tid < 240 && r < CH) {
            float v = at[r][cc];
            int cnt = 0;
            float m = -1e30f;
#pragma unroll
            for (int j = 0; j < CH; j++) {
                float u = at[r][j];
                cnt += (u > v);
                m = fmaxf(m, u);
            }
            eb[r][cc] = (cnt < TOPKN) ? expf(v - m) : 0.f;
        }
    }
    __syncthreads();

    if (tid < CH) {
        float s = 0.f;
#pragma unroll
        for (int j = 0; j < CH; j++) s += eb[tid][j];
        rsum[tid] = s;
    }
    __syncthreads();

    float* op = attn + (long)bh * CH * CH;
    for (int e = tid; e < CH * CH; e += 256) {
        int c = e / CH, d = e % CH;
        op[e] = eb[c][d] / rsum[c];
    }
}

// ---------------------------------------------------------------------------
// Fold proj_w @ blockdiag(attn) -> Wbs (bf16 split [hi|lo|hi])
// ---------------------------------------------------------------------------
__global__ void fold_proj(const float* __restrict__ projw, const float* __restrict__ attn,
                          __nv_bfloat16* __restrict__ Wbs)
{
    int idx = blockIdx.x * 256 + threadIdx.x;
    if (idx >= BATCH * DIM * DIM) return;
    int b = idx / (DIM * DIM);
    int r = idx % (DIM * DIM);
    int o = r / DIM, dg = r % DIM;
    int h = dg / CH, d = dg % CH;
    const float* pw = projw + o * DIM + h * CH;
    const float* at = attn + ((long)(b * NH + h) * CH) * CH + d;
    float s = 0.f;
#pragma unroll
    for (int c = 0; c < CH; c++) s += pw[c] * at[c * CH];
    __nv_bfloat16 hi = __float2bfloat16(s);
    __nv_bfloat16 lo = __float2bfloat16(s - __bfloat162float(hi));
    __nv_bfloat16* row = Wbs + ((long)b * DIM + o) * KP;
    row[dg]       = hi;
    row[384 + dg] = lo;
    row[768 + dg] = hi;
}

// ---------------------------------------------------------------------------
extern "C" void kernel_launch(void* const* d_in, const int* in_sizes, int n_in,
                              void* d_out, int out_size)
{
    const float* x      = (const float*)d_in[0];
    const float* qkv_w  = (const float*)d_in[1];
    const float* dw_w   = (const float*)d_in[2];
    const float* proj_w = (const float*)d_in[3];
    const float* temp   = (const float*)d_in[4];
    float* out = (float*)d_out;

    float *qkv1, *qkv2, *ssp, *inv, *gpart, *attn;
    __nv_bfloat16 *A1, *xhi, *xlo, *vhi, *vlo, *Wbs;
    cudaGetSymbolAddress((void**)&qkv1,  g_qkv1);
    cudaGetSymbolAddress((void**)&qkv2,  g_qkv2);
    cudaGetSymbolAddress((void**)&ssp,   g_ssp);
    cudaGetSymbolAddress((void**)&inv,   g_inv);
    cudaGetSymbolAddress((void**)&gpart, g_gpart);
    cudaGetSymbolAddress((void**)&attn,  g_attn);
    cudaGetSymbolAddress((void**)&A1,    g_A1);
    cudaGetSymbolAddress((void**)&xhi,   g_xhi);
    cudaGetSymbolAddress((void**)&xlo,   g_xlo);
    cudaGetSymbolAddress((void**)&vhi,   g_vhi);
    cudaGetSymbolAddress((void**)&vlo,   g_vlo);
    cudaGetSymbolAddress((void**)&Wbs,   g_Wbs);

    cudaFuncSetAttribute(gemm_split, cudaFuncAttributeMaxDynamicSharedMemorySize, GEMM_SMEM);

    // 0) operand prep (no transposes)
    split_w<<<(C3 * DIM + 255) / 256, 256>>>(qkv_w, A1);
    split_c<<<(int)(((long)BATCH * DIM * HWD / 4) / 256), 256>>>(x, xhi, xlo);

    // 1) qkv = qkv_w @ x
    gemm_split<<<dim3(C3 / BM, HWD / BN, BATCH), 256, GEMM_SMEM>>>(
        A1, 0L, xhi, xlo, qkv1, (long)C3 * HWD);

    // 2) depthwise 3x3: q/k -> fp32 + norms, v -> bf16 hi/lo planes
    dwconv3<<<BATCH * C3 * NSTRIP, 256>>>(qkv1, dw_w, qkv2, ssp, vhi, vlo);
    norm_fin<<<(BATCH * 768 + 255) / 256, 256>>>(ssp, inv);

    // 3) Gram partials, then fused scale+topk+softmax
    gram_partial<<<dim3(GCH, BATCH * NH), 256>>>(qkv2, gpart);
    attn_fuse<<<BATCH * NH, 256>>>(gpart, inv, temp, attn);

    // 4) fold proj @ blockdiag(attn)
    fold_proj<<<(BATCH * DIM * DIM + 255) / 256, 256>>>(proj_w, attn, Wbs);

    // 5) out = Wb @ v
    gemm_split<<<dim3(DIM / BM, HWD / BN, BATCH), 256, GEMM_SMEM>>>(
        Wbs, (long)DIM * KP, vhi, vlo, out, (long)DIM * HWD);
}

// round 15
// speedup vs baseline: 1.3087x; 1.0884x over previous
#include <cuda_runtime.h>
#include <cuda_bf16.h>
#include <cuda_fp16.h>
#include <math.h>
#include <stdint.h>

// ---------------------------------------------------------------------------
// Problem constants
// ---------------------------------------------------------------------------
constexpr int BATCH = 8;
constexpr int DIM   = 384;
constexpr int NH    = 8;
constexpr int CH    = 48;
constexpr int HWD   = 16384;  // 128*128
constexpr int C3    = 1152;
constexpr int TOPKN = 7;

// split-precision GEMM1 constants (R12 structure, bf16, 3-term)
constexpr int KP     = 1152;     // K' = 3*384 (hi*hi, lo*hi, hi*lo)
constexpr int KC     = 64;
constexpr int NCHUNK = KP / KC;  // 18
constexpr int BM     = 128;
constexpr int BN     = 128;
constexpr int ATILE  = BM * 128;       // A: 128 rows x 128B
constexpr int BTILE  = KC * 256;       // B: 64 k-rows x 256B
constexpr int STAGE  = ATILE + BTILE;  // 32 KB
constexpr int NSTAGE = 3;
constexpr int GEMM_SMEM = NSTAGE * STAGE;   // 96 KB

// GEMM2 (fp16): A' = [Wh|Wl] 768 cols, B = vh only, 12 chunks
constexpr int KP2     = 768;
constexpr int NCHUNK2 = KP2 / KC;  // 12

constexpr int GCH = 32;        // gram chunks

// dwconv strips
constexpr int SROWS = 32;
constexpr int NSTRIP = 128 / SROWS;       // 4
constexpr int SPITCH = 136;

// ---------------------------------------------------------------------------
// Scratch (device globals)
// ---------------------------------------------------------------------------
__device__ float g_qkv1[(size_t)BATCH * C3 * HWD];
__device__ float g_qkv2[(size_t)BATCH * C3 * HWD];   // only q,k region used
__device__ float g_ssp[BATCH * 768 * NSTRIP];
__device__ float g_inv[BATCH * 768];
__device__ float g_gpart[(size_t)GCH * BATCH * NH * CH * CH];
__device__ float g_attn[BATCH * NH * CH * CH];
__device__ __nv_bfloat16 g_A1[(size_t)C3 * KP];
__device__ __nv_bfloat16 g_xhi[(size_t)BATCH * DIM * HWD];
__device__ __nv_bfloat16 g_xlo[(size_t)BATCH * DIM * HWD];
__device__ __half g_vh[(size_t)BATCH * DIM * HWD];
__device__ __half g_Wf[(size_t)BATCH * DIM * KP2];

// ---------------------------------------------------------------------------
// sm_80-portable PTX helpers
// ---------------------------------------------------------------------------
__device__ __forceinline__ uint32_t smem_u32(const void* p) {
    uint32_t a;
    asm("{ .reg .u64 t; cvta.to.shared.u64 t, %1; cvt.u32.u64 %0, t; }" : "=r"(a) : "l"(p));
    return a;
}

__device__ __forceinline__ void cp16(uint32_t saddr, const void* gaddr) {
    asm volatile("cp.async.cg.shared.global [%0], [%1], 16;" :: "r"(saddr), "l"(gaddr));
}
#define CP_COMMIT() asm volatile("cp.async.commit_group;" ::: "memory")

__device__ __forceinline__ void ldmx4(uint32_t* r, uint32_t addr) {
    asm volatile("ldmatrix.sync.aligned.m8n8.x4.shared.b16 {%0,%1,%2,%3}, [%4];"
                 : "=r"(r[0]), "=r"(r[1]), "=r"(r[2]), "=r"(r[3]) : "r"(addr));
}

__device__ __forceinline__ void ldmx4t(uint32_t* r, uint32_t addr) {
    asm volatile("ldmatrix.sync.aligned.m8n8.x4.trans.shared.b16 {%0,%1,%2,%3}, [%4];"
                 : "=r"(r[0]), "=r"(r[1]), "=r"(r[2]), "=r"(r[3]) : "r"(addr));
}

__device__ __forceinline__ void mma16816(float* c, const uint32_t* a, const uint32_t* b) {
    asm volatile(
        "mma.sync.aligned.m16n8k16.row.col.f32.bf16.bf16.f32 "
        "{%0,%1,%2,%3}, {%4,%5,%6,%7}, {%8,%9}, {%0,%1,%2,%3};"
        : "+f"(c[0]), "+f"(c[1]), "+f"(c[2]), "+f"(c[3])
        : "r"(a[0]), "r"(a[1]), "r"(a[2]), "r"(a[3]), "r"(b[0]), "r"(b[1]));
}

__device__ __forceinline__ void mma16816h(float* c, const uint32_t* a, const uint32_t* b) {
    asm volatile(
        "mma.sync.aligned.m16n8k16.row.col.f32.f16.f16.f32 "
        "{%0,%1,%2,%3}, {%4,%5,%6,%7}, {%8,%9}, {%0,%1,%2,%3};"
        : "+f"(c[0]), "+f"(c[1]), "+f"(c[2]), "+f"(c[3])
        : "r"(a[0]), "r"(a[1]), "r"(a[2]), "r"(a[3]), "r"(b[0]), "r"(b[1]));
}

// ---------------------------------------------------------------------------
// GEMM1: split-precision bf16 (R12 verbatim).
//   C[bz][m][n] = sum_{k'} A'[m][k'] * B'[n][seg(k')]
// A' rows [hi|lo|hi] (KP cols). B planes Bhi/Blo [bz][384][HWD].
// Chunk c: seg = (c<12 ? hi : lo), k0 = (c%6)*64.
// ---------------------------------------------------------------------------
__global__ void __launch_bounds__(256, 2)
gemm_split(const __nv_bfloat16* __restrict__ A, long aBatchStride,
           const __nv_bfloat16* __restrict__ Bhi,
           const __nv_bfloat16* __restrict__ Blo,
           float* __restrict__ C, long cBatchStride)
{
    extern __shared__ char sm[];
    const uint32_t smBase = smem_u32(sm);

    const int tid = threadIdx.x;
    const int wid = tid >> 5, l = tid & 31;
    const int wm = wid >> 2, wn = wid & 3;
    const int bm0 = blockIdx.x * BM;
    const int bn0 = blockIdx.y * BN;
    const int bz  = blockIdx.z;

    const __nv_bfloat16* Ab  = A + (long)bz * aBatchStride + (long)bm0 * KP;
    const __nv_bfloat16* Bhb = Bhi + (long)bz * DIM * HWD;
    const __nv_bfloat16* Blb = Blo + (long)bz * DIM * HWD;
    float* Cb = C + (long)bz * cBatchStride + (long)bm0 * HWD + bn0;

    const int ldr = tid >> 3, ldq = tid & 7;
    const int bro = tid >> 2, bu0 = tid & 3;

    auto load_chunk = [&](int c, int s) {
        const uint32_t sA = smBase + s * STAGE;
        const uint32_t sB = sA + ATILE;
        const __nv_bfloat16* ac = Ab + c * KC;
#pragma unroll
        for (int i = 0; i < 4; i++) {
            int r = ldr + i * 32;
            int u = ldq ^ (r & 7);
            cp16(sA + r * 128 + u * 16, ac + (long)r * KP + ldq * 8);
        }
        const __nv_bfloat16* bsrc = (c < 12) ? Bhb : Blb;
        const int k0 = (c % 6) * KC;
        const __nv_bfloat16* brow = bsrc + (long)(k0 + bro) * HWD + bn0;
#pragma unroll
        for (int i = 0; i < 4; i++) {
            int u = bu0 + 4 * i;
            cp16(sB + bro * 256 + ((u ^ (bro & 7)) * 16), brow + u * 8);
        }
        CP_COMMIT();
    };

    float acc[4][4][4] = {};

    const int l7 = l & 7;
    const int a_x = l >> 4;
    int arow[4];
#pragma unroll
    for (int mi = 0; mi < 4; mi++)
        arow[mi] = (wm * 64 + mi * 16 + (l & 15)) * 128;
    const int b_row_l = l & 15;
    const int b_u_l   = wn * 4 + (l >> 4);

    load_chunk(0, 0);
    load_chunk(1, 1);

    for (int c = 0; c < NCHUNK; c++) {
        if (c + 2 < NCHUNK) {
            asm volatile("cp.async.wait_group 1;" ::: "memory");
        } else {
            asm volatile("cp.async.wait_group 0;" ::: "memory");
        }
        __syncthreads();
        if (c + 2 < NCHUNK) load_chunk(c + 2, (c + 2) % NSTAGE);

        const int s = c % NSTAGE;
        const uint32_t sA = smBase + s * STAGE;
        const uint32_t sB = sA + ATILE;

#pragma unroll
        for (int kk = 0; kk < 4; kk++) {
            uint32_t afr[4][4];
#pragma unroll
            for (int mi = 0; mi < 4; mi++) {
                uint32_t u = (uint32_t)((kk * 2 + a_x) ^ l7);
                ldmx4(afr[mi], sA + arow[mi] + u * 16);
            }
            uint32_t bfr[4][2];
#pragma unroll
            for (int g = 0; g < 2; g++) {
                uint32_t t4[4];
                int row = kk * 16 + b_row_l;
                int u = b_u_l + g * 2;
                ldmx4t(t4, sB + row * 256 + ((u ^ (row & 7)) * 16));
                bfr[2 * g][0] = t4[0]; bfr[2 * g][1] = t4[1];
                bfr[2 * g + 1][0] = t4[2]; bfr[2 * g + 1][1] = t4[3];
            }
#pragma unroll
            for (int mi = 0; mi < 4; mi++)
#pragma unroll
                for (int ni = 0; ni < 4; ni++)
                    mma16816(acc[mi][ni], afr[mi], bfr[ni]);
        }
        __syncthreads();
    }

    const int crow = l >> 2, ccol = (l & 3) * 2;
#pragma unroll
    for (int mi = 0; mi < 4; mi++) {
#pragma unroll
        for (int ni = 0; ni < 4; ni++) {
            float* p = Cb + (long)(wm * 64 + mi * 16 + crow) * HWD + wn * 32 + ni * 8 + ccol;
            *(float2*)p = make_float2(acc[mi][ni][0], acc[mi][ni][1]);
            *(float2*)(p + 8L * HWD) = make_float2(acc[mi][ni][2], acc[mi][ni][3]);
        }
    }
}

// ---------------------------------------------------------------------------
// GEMM2: fp16, A' = [Wh|Wl] (768 cols, K-major rows), B = vh plane only.
//   out = (Wh + Wl) @ vh.  Chunk c: A cols c*64.., B k0 = (c%6)*64.
// ---------------------------------------------------------------------------
__global__ void __launch_bounds__(256, 2)
gemm2_f16(const __half* __restrict__ A, long aBatchStride,
          const __half* __restrict__ Bv,
          float* __restrict__ C, long cBatchStride)
{
    extern __shared__ char sm[];
    const uint32_t smBase = smem_u32(sm);

    const int tid = threadIdx.x;
    const int wid = tid >> 5, l = tid & 31;
    const int wm = wid >> 2, wn = wid & 3;
    const int bm0 = blockIdx.x * BM;
    const int bn0 = blockIdx.y * BN;
    const int bz  = blockIdx.z;

    const __half* Ab = A + (long)bz * aBatchStride + (long)bm0 * KP2;
    const __half* Bb = Bv + (long)bz * DIM * HWD;
    float* Cb = C + (long)bz * cBatchStride + (long)bm0 * HWD + bn0;

    const int ldr = tid >> 3, ldq = tid & 7;
    const int bro = tid >> 2, bu0 = tid & 3;

    auto load_chunk = [&](int c, int s) {
        const uint32_t sA = smBase + s * STAGE;
        const uint32_t sB = sA + ATILE;
        const __half* ac = Ab + c * KC;
#pragma unroll
        for (int i = 0; i < 4; i++) {
            int r = ldr + i * 32;
            int u = ldq ^ (r & 7);
            cp16(sA + r * 128 + u * 16, ac + (long)r * KP2 + ldq * 8);
        }
        const int k0 = (c % 6) * KC;
        const __half* brow = Bb + (long)(k0 + bro) * HWD + bn0;
#pragma unroll
        for (int i = 0; i < 4; i++) {
            int u = bu0 + 4 * i;
            cp16(sB + bro * 256 + ((u ^ (bro & 7)) * 16), brow + u * 8);
        }
        CP_COMMIT();
    };

    float acc[4][4][4] = {};

    const int l7 = l & 7;
    const int a_x = l >> 4;
    int arow[4];
#pragma unroll
    for (int mi = 0; mi < 4; mi++)
        arow[mi] = (wm * 64 + mi * 16 + (l & 15)) * 128;
    const int b_row_l = l & 15;
    const int b_u_l   = wn * 4 + (l >> 4);

    load_chunk(0, 0);
    load_chunk(1, 1);

    for (int c = 0; c < NCHUNK2; c++) {
        if (c + 2 < NCHUNK2) {
            asm volatile("cp.async.wait_group 1;" ::: "memory");
        } else {
            asm volatile("cp.async.wait_group 0;" ::: "memory");
        }
        __syncthreads();
        if (c + 2 < NCHUNK2) load_chunk(c + 2, (c + 2) % NSTAGE);

        const int s = c % NSTAGE;
        const uint32_t sA = smBase + s * STAGE;
        const uint32_t sB = sA + ATILE;

#pragma unroll
        for (int kk = 0; kk < 4; kk++) {
            uint32_t afr[4][4];
#pragma unroll
            for (int mi = 0; mi < 4; mi++) {
                uint32_t u = (uint32_t)((kk * 2 + a_x) ^ l7);
                ldmx4(afr[mi], sA + arow[mi] + u * 16);
            }
            uint32_t bfr[4][2];
#pragma unroll
            for (int g = 0; g < 2; g++) {
                uint32_t t4[4];
                int row = kk * 16 + b_row_l;
                int u = b_u_l + g * 2;
                ldmx4t(t4, sB + row * 256 + ((u ^ (row & 7)) * 16));
                bfr[2 * g][0] = t4[0]; bfr[2 * g][1] = t4[1];
                bfr[2 * g + 1][0] = t4[2]; bfr[2 * g + 1][1] = t4[3];
            }
#pragma unroll
            for (int mi = 0; mi < 4; mi++)
#pragma unroll
                for (int ni = 0; ni < 4; ni++)
                    mma16816h(acc[mi][ni], afr[mi], bfr[ni]);
        }
        __syncthreads();
    }

    const int crow = l >> 2, ccol = (l & 3) * 2;
#pragma unroll
    for (int mi = 0; mi < 4; mi++) {
#pragma unroll
        for (int ni = 0; ni < 4; ni++) {
            float* p = Cb + (long)(wm * 64 + mi * 16 + crow) * HWD + wn * 32 + ni * 8 + ccol;
            *(float2*)p = make_float2(acc[mi][ni][0], acc[mi][ni][1]);
            *(float2*)(p + 8L * HWD) = make_float2(acc[mi][ni][2], acc[mi][ni][3]);
        }
    }
}

// ---------------------------------------------------------------------------
// Split qkv_w -> A' [1152][1152] bf16 = [hi | lo | hi]
// ---------------------------------------------------------------------------
__global__ void split_w(const float* __restrict__ w, __nv_bfloat16* __restrict__ o)
{
    int idx = blockIdx.x * 256 + threadIdx.x;
    if (idx >= C3 * DIM) return;
    int m = idx / DIM, k = idx % DIM;
    float v = w[idx];
    __nv_bfloat16 hi = __float2bfloat16(v);
    __nv_bfloat16 lo = __float2bfloat16(v - __bfloat162float(hi));
    o[(long)m * KP + k]       = hi;
    o[(long)m * KP + 384 + k] = lo;
    o[(long)m * KP + 768 + k] = hi;
}

// ---------------------------------------------------------------------------
// split_c: fp32 [b][384][HWD] -> hi/lo bf16 planes, same layout
// ---------------------------------------------------------------------------
__global__ void __launch_bounds__(256)
split_c(const float* __restrict__ src, __nv_bfloat16* __restrict__ hi,
        __nv_bfloat16* __restrict__ lo)
{
    long i4 = (long)blockIdx.x * 256 + threadIdx.x;   // float4 index
    float4 v = ((const float4*)src)[i4];
    __nv_bfloat16 hx = __float2bfloat16(v.x);
    __nv_bfloat16 hy = __float2bfloat16(v.y);
    __nv_bfloat16 hz = __float2bfloat16(v.z);
    __nv_bfloat16 hw = __float2bfloat16(v.w);
    __nv_bfloat162 h01, h23, l01, l23;
    h01.x = hx; h01.y = hy; h23.x = hz; h23.y = hw;
    l01.x = __float2bfloat16(v.x - __bfloat162float(hx));
    l01.y = __float2bfloat16(v.y - __bfloat162float(hy));
    l23.x = __float2bfloat16(v.z - __bfloat162float(hz));
    l23.y = __float2bfloat16(v.w - __bfloat162float(hw));
    ((__nv_bfloat162*)hi)[i4 * 2]     = h01;
    ((__nv_bfloat162*)hi)[i4 * 2 + 1] = h23;
    ((__nv_bfloat162*)lo)[i4 * 2]     = l01;
    ((__nv_bfloat162*)lo)[i4 * 2 + 1] = l23;
}

// ---------------------------------------------------------------------------
// Depthwise 3x3: q/k -> fp32 + norms, v -> single fp16 plane
// ---------------------------------------------------------------------------
__global__ void __launch_bounds__(256)
dwconv3(const float* __restrict__ in, const float* __restrict__ w,
        float* __restrict__ out, float* __restrict__ ssp,
        __half* __restrict__ vh)
{
    __shared__ float pl[(SROWS + 2) * SPITCH];
    __shared__ float red[256];

    const int strip = blockIdx.x & (NSTRIP - 1);
    const int c = (blockIdx.x >> 2) % C3;
    const int b = blockIdx.x / (NSTRIP * C3);
    const int tid = threadIdx.x;

#pragma unroll
    for (int i = tid; i < (SROWS + 2) * SPITCH; i += 256)
        pl[i] = 0.f;
    __syncthreads();

    const int r0 = strip * SROWS;
    const float* ip = in + ((long)b * C3 + c) * HWD;

    {
        const int rlo = (strip == 0) ? 1 : 0;
        const int rhi = (strip == NSTRIP - 1) ? SROWS : SROWS + 1;
        const int njobs = (rhi - rlo + 1) * 32;
        for (int i = tid; i < njobs; i += 256) {
            int lr = rlo + (i >> 5);
            int x4 = (i & 31) * 4;
            *(float4*)&pl[lr * SPITCH + 4 + x4] =
                *(const float4*)&ip[(long)(r0 - 1 + lr) * 128 + x4];
        }
    }

    const float* wp = w + c * 9;
    float w0 = wp[0], w1 = wp[1], w2 = wp[2];
    float w3 = wp[3], w4 = wp[4], w5 = wp[5];
    float w6 = wp[6], w7 = wp[7], w8 = wp[8];
    __syncthreads();

    const int tx = tid & 31, ty = tid >> 5;
    const int x4 = tx * 4;
    const int h0 = ty * 4;

    float4 Ar[3], Br[3], Cr[3];
    auto loadrow = [&](int srow, int slot) {
        int idx = srow * SPITCH + 4 + x4;
        Ar[slot] = *(float4*)&pl[idx - 4];
        Br[slot] = *(float4*)&pl[idx];
        Cr[slot] = *(float4*)&pl[idx + 4];
    };
    loadrow(h0 + 0, 0);
    loadrow(h0 + 1, 1);
    loadrow(h0 + 2, 2);

    const bool isV = (c >= 768);
    float4* op4 = (float4*)(out + ((long)b * C3 + c) * HWD + (long)r0 * 128);
    __half2* vh2 = nullptr;
    if (isV) {
        long off = ((long)b * DIM + (c - 768)) * HWD + (long)r0 * 128;
        vh2 = (__half2*)(vh + off);
    }
    float ss = 0.f;

#pragma unroll
    for (int i = 0; i < 4; i++) {
        const int s0 = i % 3, s1 = (i + 1) % 3, s2 = (i + 2) % 3;
        float4 s;
        s.x = w0 * Ar[s0].w + w1 * Br[s0].x + w2 * Br[s0].y
            + w3 * Ar[s1].w + w4 * Br[s1].x + w5 * Br[s1].y
            + w6 * Ar[s2].w + w7 * Br[s2].x + w8 * Br[s2].y;
        s.y = w0 * Br[s0].x + w1 * Br[s0].y + w2 * Br[s0].z
            + w3 * Br[s1].x + w4 * Br[s1].y + w5 * Br[s1].z
            + w6 * Br[s2].x + w7 * Br[s2].y + w8 * Br[s2].z;
        s.z = w0 * Br[s0].y + w1 * Br[s0].z + w2 * Br[s0].w
            + w3 * Br[s1].y + w4 * Br[s1].z + w5 * Br[s1].w
            + w6 * Br[s2].y + w7 * Br[s2].z + w8 * Br[s2].w;
        s.w = w0 * Br[s0].z + w1 * Br[s0].w + w2 * Cr[s0].x
            + w3 * Br[s1].z + w4 * Br[s1].w + w5 * Cr[s1].x
            + w6 * Br[s2].z + w7 * Br[s2].w + w8 * Cr[s2].x;
        if (isV) {
            int e2 = (h0 + i) * 64 + tx * 2;
            vh2[e2]     = __floats2half2_rn(s.x, s.y);
            vh2[e2 + 1] = __floats2half2_rn(s.z, s.w);
        } else {
            op4[(h0 + i) * 32 + tx] = s;
            ss += s.x * s.x + s.y * s.y + s.z * s.z + s.w * s.w;
        }
        if (i < 3) loadrow(h0 + 3 + i, s0);
    }

    if (c < 768) {
        red[tid] = ss;
        __syncthreads();
        for (int st = 128; st > 0; st >>= 1) {
            if (tid < st) red[tid] += red[tid + st];
            __syncthreads();
        }
        if (tid == 0)
            ssp[(b * 768 + c) * NSTRIP + strip] = red[0];
    }
}

// finalize inv norms from strip partials
__global__ void norm_fin(const float* __restrict__ ssp, float* __restrict__ inv)
{
    int i = blockIdx.x * 256 + threadIdx.x;
    if (i >= BATCH * 768) return;
    float s = 0.f;
#pragma unroll
    for (int j = 0; j < NSTRIP; j++) s += ssp[i * NSTRIP + j];
    inv[i] = 1.f / fmaxf(sqrtf(s), 1e-12f);
}

// ---------------------------------------------------------------------------
// Gram partial (unchanged)
// ---------------------------------------------------------------------------
__global__ void __launch_bounds__(256)
gram_partial(const float* __restrict__ qkv2, float* __restrict__ gpart)
{
    const int chunk = blockIdx.x;
    const int bh = blockIdx.y;
    const int b = bh >> 3, h = bh & 7;
    const float* qb = qkv2 + ((long)b * C3 + h * CH) * HWD;
    const float* kb = qb + (long)DIM * HWD;

    __shared__ float qs[64][49], ks[64][49];
    const int tid = threadIdx.x;
    const int tx = tid & 15, ty = tid >> 4;
    float acc[3][3] = {};

    const int n0 = chunk * 512;
    for (int slab = 0; slab < 8; slab++) {
        const int base = n0 + slab * 64;
        __syncthreads();
#pragma unroll
        for (int j = 0; j < 3; j++) {
            int id = tid + j * 256;
            int rid = id >> 4, c4 = id & 15;
            float4 v = *(const float4*)(qb + (long)rid * HWD + base + c4 * 4);
            qs[c4 * 4 + 0][rid] = v.x; qs[c4 * 4 + 1][rid] = v.y;
            qs[c4 * 4 + 2][rid] = v.z; qs[c4 * 4 + 3][rid] = v.w;
            float4 u = *(const float4*)(kb + (long)rid * HWD + base + c4 * 4);
            ks[c4 * 4 + 0][rid] = u.x; ks[c4 * 4 + 1][rid] = u.y;
            ks[c4 * 4 + 2][rid] = u.z; ks[c4 * 4 + 3][rid] = u.w;
        }
        __syncthreads();
#pragma unroll 8
        for (int t = 0; t < 64; t++) {
            float qa[3], ka[3];
#pragma unroll
            for (int i = 0; i < 3; i++) qa[i] = qs[t][ty * 3 + i];
#pragma unroll
            for (int j = 0; j < 3; j++) ka[j] = ks[t][tx * 3 + j];
#pragma unroll
            for (int i = 0; i < 3; i++)
#pragma unroll
                for (int j = 0; j < 3; j++)
                    acc[i][j] += qa[i] * ka[j];
        }
    }
    float* op = gpart + ((long)chunk * 64 + bh) * (CH * CH);
#pragma unroll
    for (int i = 0; i < 3; i++)
#pragma unroll
        for (int j = 0; j < 3; j++)
            op[(ty * 3 + i) * CH + tx * 3 + j] = acc[i][j];
}

__global__ void gram_scale(const float* __restrict__ gpart, const float* __restrict__ inv,
                           const float* __restrict__ temp, float* __restrict__ attn)
{
    int idx = blockIdx.x * 256 + threadIdx.x;
    if (idx >= 64 * CH * CH) return;
    int bh = idx / (CH * CH), r = idx % (CH * CH);
    int c = r / CH, d = r % CH;
    int b = bh >> 3, h = bh & 7;
    float s = 0.f;
#pragma unroll
    for (int ck = 0; ck < GCH; ck++) s += gpart[((long)ck * 64 + bh) * (CH * CH) + r];
    float iq = inv[b * 768 + h * CH + c];
    float ik = inv[b * 768 + 384 + h * CH + d];
    attn[idx] = s * iq * ik * temp[h];
}

__global__ void topk_softmax(float* __restrict__ attn)
{
    int row = blockIdx.x;
    float* p = attn + (long)row * CH;
    __shared__ float s[CH], e[CH];
    int i = threadIdx.x;
    if (i < CH) s[i] = p[i];
    __syncthreads();
    if (i < CH) {
        float v = s[i];
        int cnt = 0;
        float m = -1e30f;
#pragma unroll
        for (int j = 0; j < CH; j++) {
            cnt += (s[j] > v);
            m = fmaxf(m, s[j]);
        }
        e[i] = (cnt < TOPKN) ? expf(v - m) : 0.f;
    }
    __syncthreads();
    if (i < CH) {
        float sum = 0.f;
#pragma unroll
        for (int j = 0; j < CH; j++) sum += e[j];
        p[i] = e[i] / sum;
    }
}

// ---------------------------------------------------------------------------
// Fold proj_w @ blockdiag(attn) -> Wf fp16 [b][o][Wh(384)|Wl(384)]
// ---------------------------------------------------------------------------
__global__ void fold_proj(const float* __restrict__ projw, const float* __restrict__ attn,
                          __half* __restrict__ Wf)
{
    int idx = blockIdx.x * 256 + threadIdx.x;
    if (idx >= BATCH * DIM * DIM) return;
    int b = idx / (DIM * DIM);
    int r = idx % (DIM * DIM);
    int o = r / DIM, dg = r % DIM;
    int h = dg / CH, d = dg % CH;
    const float* pw = projw + o * DIM + h * CH;
    const float* at = attn + ((long)(b * NH + h) * CH) * CH + d;
    float s = 0.f;
#pragma unroll
    for (int c = 0; c < CH; c++) s += pw[c] * at[c * CH];
    __half hi = __float2half_rn(s);
    __half lo = __float2half_rn(s - __half2float(hi));
    __half* row = Wf + ((long)b * DIM + o) * KP2;
    row[dg]       = hi;
    row[384 + dg] = lo;
}

// ---------------------------------------------------------------------------
extern "C" void kernel_launch(void* const* d_in, const int* in_sizes, int n_in,
                              void* d_out, int out_size)
{
    const float* x      = (const float*)d_in[0];
    const float* qkv_w  = (const float*)d_in[1];
    const float* dw_w   = (const float*)d_in[2];
    const float* proj_w = (const float*)d_in[3];
    const float* temp   = (const float*)d_in[4];
    float* out = (float*)d_out;

    float *qkv1, *qkv2, *ssp, *inv, *gpart, *attn;
    __nv_bfloat16 *A1, *xhi, *xlo;
    __half *vh, *Wf;
    cudaGetSymbolAddress((void**)&qkv1,  g_qkv1);
    cudaGetSymbolAddress((void**)&qkv2,  g_qkv2);
    cudaGetSymbolAddress((void**)&ssp,   g_ssp);
    cudaGetSymbolAddress((void**)&inv,   g_inv);
    cudaGetSymbolAddress((void**)&gpart, g_gpart);
    cudaGetSymbolAddress((void**)&attn,  g_attn);
    cudaGetSymbolAddress((void**)&A1,    g_A1);
    cudaGetSymbolAddress((void**)&xhi,   g_xhi);
    cudaGetSymbolAddress((void**)&xlo,   g_xlo);
    cudaGetSymbolAddress((void**)&vh,    g_vh);
    cudaGetSymbolAddress((void**)&Wf,    g_Wf);

    cudaFuncSetAttribute(gemm_split, cudaFuncAttributeMaxDynamicSharedMemorySize, GEMM_SMEM);
    cudaFuncSetAttribute(gemm2_f16, cudaFuncAttributeMaxDynamicSharedMemorySize, GEMM_SMEM);

    // 0) operand prep (no transposes)
    split_w<<<(C3 * DIM + 255) / 256, 256>>>(qkv_w, A1);
    split_c<<<(int)(((long)BATCH * DIM * HWD / 4) / 256), 256>>>(x, xhi, xlo);

    // 1) qkv = qkv_w @ x   (bf16 3-term, proven)
    gemm_split<<<dim3(C3 / BM, HWD / BN, BATCH), 256, GEMM_SMEM>>>(
        A1, 0L, xhi, xlo, qkv1, (long)C3 * HWD);

    // 2) depthwise 3x3: q/k -> fp32 + norms, v -> fp16 plane
    dwconv3<<<BATCH * C3 * NSTRIP, 256>>>(qkv1, dw_w, qkv2, ssp, vh);
    norm_fin<<<(BATCH * 768 + 255) / 256, 256>>>(ssp, inv);

    // 3) Gram + scale + topk softmax (R12 structure)
    gram_partial<<<dim3(GCH, BATCH * NH), 256>>>(qkv2, gpart);
    gram_scale<<<(64 * CH * CH + 255) / 256, 256>>>(gpart, inv, temp, attn);
    topk_softmax<<<BATCH * NH * CH, 64>>>(attn);

    // 4) fold proj @ blockdiag(attn) -> fp16 [Wh|Wl]
    fold_proj<<<(BATCH * DIM * DIM + 255) / 256, 256>>>(proj_w, attn, Wf);

    // 5) out = (Wh + Wl) @ vh   (fp16, 12 chunks)
    gemm2_f16<<<dim3(DIM / BM, HWD / BN, BATCH), 256, GEMM_SMEM>>>(
        Wf, (long)DIM * KP2, vh, out, (long)DIM * HWD);
}

// round 16
// speedup vs baseline: 1.3956x; 1.0664x over previous
#include <cuda_runtime.h>
#include <cuda_bf16.h>
#include <cuda_fp16.h>
#include <math.h>
#include <stdint.h>

// ---------------------------------------------------------------------------
// Problem constants
// ---------------------------------------------------------------------------
constexpr int BATCH = 8;
constexpr int DIM   = 384;
constexpr int NH    = 8;
constexpr int CH    = 48;
constexpr int HWD   = 16384;  // 128*128
constexpr int C3    = 1152;
constexpr int TOPKN = 7;

// split-precision GEMM1 constants (R12 structure, bf16, 3-term)
constexpr int KP     = 1152;     // K' = 3*384 (hi*hi, lo*hi, hi*lo)
constexpr int KC     = 64;
constexpr int NCHUNK = KP / KC;  // 18
constexpr int BM     = 128;
constexpr int BN     = 128;
constexpr int ATILE  = BM * 128;       // A: 128 rows x 128B
constexpr int BTILE  = KC * 256;       // B: 64 k-rows x 256B
constexpr int STAGE  = ATILE + BTILE;  // 32 KB
constexpr int NSTAGE = 3;
constexpr int GEMM_SMEM = NSTAGE * STAGE;   // 96 KB

// GEMM2 (fp16, single term): A = Wh (384 cols), B = vh, 6 chunks
constexpr int KP2     = 384;
constexpr int NCHUNK2 = KP2 / KC;  // 6

constexpr int GCH = 32;        // gram chunks

// dwconv strips
constexpr int SROWS = 32;
constexpr int NSTRIP = 128 / SROWS;       // 4
constexpr int SPITCH = 136;

// ---------------------------------------------------------------------------
// Scratch (device globals)
// ---------------------------------------------------------------------------
__device__ float g_qkv1[(size_t)BATCH * C3 * HWD];
__device__ float g_qkv2[(size_t)BATCH * C3 * HWD];   // only q,k region used
__device__ float g_ssp[BATCH * 768 * NSTRIP];
__device__ float g_inv[BATCH * 768];
__device__ float g_gpart[(size_t)GCH * BATCH * NH * CH * CH];
__device__ float g_attn[BATCH * NH * CH * CH];
__device__ __nv_bfloat16 g_A1[(size_t)C3 * KP];
__device__ __nv_bfloat16 g_xhi[(size_t)BATCH * DIM * HWD];
__device__ __nv_bfloat16 g_xlo[(size_t)BATCH * DIM * HWD];
__device__ __half g_vh[(size_t)BATCH * DIM * HWD];
__device__ __half g_Wf[(size_t)BATCH * DIM * KP2];

// ---------------------------------------------------------------------------
// sm_80-portable PTX helpers
// ---------------------------------------------------------------------------
__device__ __forceinline__ uint32_t smem_u32(const void* p) {
    uint32_t a;
    asm("{ .reg .u64 t; cvta.to.shared.u64 t, %1; cvt.u32.u64 %0, t; }" : "=r"(a) : "l"(p));
    return a;
}

__device__ __forceinline__ void cp16(uint32_t saddr, const void* gaddr) {
    asm volatile("cp.async.cg.shared.global [%0], [%1], 16;" :: "r"(saddr), "l"(gaddr));
}
#define CP_COMMIT() asm volatile("cp.async.commit_group;" ::: "memory")

__device__ __forceinline__ void ldmx4(uint32_t* r, uint32_t addr) {
    asm volatile("ldmatrix.sync.aligned.m8n8.x4.shared.b16 {%0,%1,%2,%3}, [%4];"
                 : "=r"(r[0]), "=r"(r[1]), "=r"(r[2]), "=r"(r[3]) : "r"(addr));
}

__device__ __forceinline__ void ldmx4t(uint32_t* r, uint32_t addr) {
    asm volatile("ldmatrix.sync.aligned.m8n8.x4.trans.shared.b16 {%0,%1,%2,%3}, [%4];"
                 : "=r"(r[0]), "=r"(r[1]), "=r"(r[2]), "=r"(r[3]) : "r"(addr));
}

__device__ __forceinline__ void mma16816(float* c, const uint32_t* a, const uint32_t* b) {
    asm volatile(
        "mma.sync.aligned.m16n8k16.row.col.f32.bf16.bf16.f32 "
        "{%0,%1,%2,%3}, {%4,%5,%6,%7}, {%8,%9}, {%0,%1,%2,%3};"
        : "+f"(c[0]), "+f"(c[1]), "+f"(c[2]), "+f"(c[3])
        : "r"(a[0]), "r"(a[1]), "r"(a[2]), "r"(a[3]), "r"(b[0]), "r"(b[1]));
}

__device__ __forceinline__ void mma16816h(float* c, const uint32_t* a, const uint32_t* b) {
    asm volatile(
        "mma.sync.aligned.m16n8k16.row.col.f32.f16.f16.f32 "
        "{%0,%1,%2,%3}, {%4,%5,%6,%7}, {%8,%9}, {%0,%1,%2,%3};"
        : "+f"(c[0]), "+f"(c[1]), "+f"(c[2]), "+f"(c[3])
        : "r"(a[0]), "r"(a[1]), "r"(a[2]), "r"(a[3]), "r"(b[0]), "r"(b[1]));
}

// ---------------------------------------------------------------------------
// GEMM1: split-precision bf16 (R12 verbatim).
//   C[bz][m][n] = sum_{k'} A'[m][k'] * B'[n][seg(k')]
// A' rows [hi|lo|hi] (KP cols). B planes Bhi/Blo [bz][384][HWD].
// Chunk c: seg = (c<12 ? hi : lo), k0 = (c%6)*64.
// ---------------------------------------------------------------------------
__global__ void __launch_bounds__(256, 2)
gemm_split(const __nv_bfloat16* __restrict__ A, long aBatchStride,
           const __nv_bfloat16* __restrict__ Bhi,
           const __nv_bfloat16* __restrict__ Blo,
           float* __restrict__ C, long cBatchStride)
{
    extern __shared__ char sm[];
    const uint32_t smBase = smem_u32(sm);

    const int tid = threadIdx.x;
    const int wid = tid >> 5, l = tid & 31;
    const int wm = wid >> 2, wn = wid & 3;
    const int bm0 = blockIdx.x * BM;
    const int bn0 = blockIdx.y * BN;
    const int bz  = blockIdx.z;

    const __nv_bfloat16* Ab  = A + (long)bz * aBatchStride + (long)bm0 * KP;
    const __nv_bfloat16* Bhb = Bhi + (long)bz * DIM * HWD;
    const __nv_bfloat16* Blb = Blo + (long)bz * DIM * HWD;
    float* Cb = C + (long)bz * cBatchStride + (long)bm0 * HWD + bn0;

    const int ldr = tid >> 3, ldq = tid & 7;
    const int bro = tid >> 2, bu0 = tid & 3;

    auto load_chunk = [&](int c, int s) {
        const uint32_t sA = smBase + s * STAGE;
        const uint32_t sB = sA + ATILE;
        const __nv_bfloat16* ac = Ab + c * KC;
#pragma unroll
        for (int i = 0; i < 4; i++) {
            int r = ldr + i * 32;
            int u = ldq ^ (r & 7);
            cp16(sA + r * 128 + u * 16, ac + (long)r * KP + ldq * 8);
        }
        const __nv_bfloat16* bsrc = (c < 12) ? Bhb : Blb;
        const int k0 = (c % 6) * KC;
        const __nv_bfloat16* brow = bsrc + (long)(k0 + bro) * HWD + bn0;
#pragma unroll
        for (int i = 0; i < 4; i++) {
            int u = bu0 + 4 * i;
            cp16(sB + bro * 256 + ((u ^ (bro & 7)) * 16), brow + u * 8);
        }
        CP_COMMIT();
    };

    float acc[4][4][4] = {};

    const int l7 = l & 7;
    const int a_x = l >> 4;
    int arow[4];
#pragma unroll
    for (int mi = 0; mi < 4; mi++)
        arow[mi] = (wm * 64 + mi * 16 + (l & 15)) * 128;
    const int b_row_l = l & 15;
    const int b_u_l   = wn * 4 + (l >> 4);

    load_chunk(0, 0);
    load_chunk(1, 1);

    for (int c = 0; c < NCHUNK; c++) {
        if (c + 2 < NCHUNK) {
            asm volatile("cp.async.wait_group 1;" ::: "memory");
        } else {
            asm volatile("cp.async.wait_group 0;" ::: "memory");
        }
        __syncthreads();
        if (c + 2 < NCHUNK) load_chunk(c + 2, (c + 2) % NSTAGE);

        const int s = c % NSTAGE;
        const uint32_t sA = smBase + s * STAGE;
        const uint32_t sB = sA + ATILE;

#pragma unroll
        for (int kk = 0; kk < 4; kk++) {
            uint32_t afr[4][4];
#pragma unroll
            for (int mi = 0; mi < 4; mi++) {
                uint32_t u = (uint32_t)((kk * 2 + a_x) ^ l7);
                ldmx4(afr[mi], sA + arow[mi] + u * 16);
            }
            uint32_t bfr[4][2];
#pragma unroll
            for (int g = 0; g < 2; g++) {
                uint32_t t4[4];
                int row = kk * 16 + b_row_l;
                int u = b_u_l + g * 2;
                ldmx4t(t4, sB + row * 256 + ((u ^ (row & 7)) * 16));
                bfr[2 * g][0] = t4[0]; bfr[2 * g][1] = t4[1];
                bfr[2 * g + 1][0] = t4[2]; bfr[2 * g + 1][1] = t4[3];
            }
#pragma unroll
            for (int mi = 0; mi < 4; mi++)
#pragma unroll
                for (int ni = 0; ni < 4; ni++)
                    mma16816(acc[mi][ni], afr[mi], bfr[ni]);
        }
        __syncthreads();
    }

    const int crow = l >> 2, ccol = (l & 3) * 2;
#pragma unroll
    for (int mi = 0; mi < 4; mi++) {
#pragma unroll
        for (int ni = 0; ni < 4; ni++) {
            float* p = Cb + (long)(wm * 64 + mi * 16 + crow) * HWD + wn * 32 + ni * 8 + ccol;
            *(float2*)p = make_float2(acc[mi][ni][0], acc[mi][ni][1]);
            *(float2*)(p + 8L * HWD) = make_float2(acc[mi][ni][2], acc[mi][ni][3]);
        }
    }
}

// ---------------------------------------------------------------------------
// GEMM2: fp16 single term. A = Wh [b][384 rows][384 cols], B = vh plane.
//   out = Wh @ vh.  6 chunks.
// ---------------------------------------------------------------------------
__global__ void __launch_bounds__(256, 2)
gemm2_f16(const __half* __restrict__ A, long aBatchStride,
          const __half* __restrict__ Bv,
          float* __restrict__ C, long cBatchStride)
{
    extern __shared__ char sm[];
    const uint32_t smBase = smem_u32(sm);

    const int tid = threadIdx.x;
    const int wid = tid >> 5, l = tid & 31;
    const int wm = wid >> 2, wn = wid & 3;
    const int bm0 = blockIdx.x * BM;
    const int bn0 = blockIdx.y * BN;
    const int bz  = blockIdx.z;

    const __half* Ab = A + (long)bz * aBatchStride + (long)bm0 * KP2;
    const __half* Bb = Bv + (long)bz * DIM * HWD;
    float* Cb = C + (long)bz * cBatchStride + (long)bm0 * HWD + bn0;

    const int ldr = tid >> 3, ldq = tid & 7;
    const int bro = tid >> 2, bu0 = tid & 3;

    auto load_chunk = [&](int c, int s) {
        const uint32_t sA = smBase + s * STAGE;
        const uint32_t sB = sA + ATILE;
        const __half* ac = Ab + c * KC;
#pragma unroll
        for (int i = 0; i < 4; i++) {
            int r = ldr + i * 32;
            int u = ldq ^ (r & 7);
            cp16(sA + r * 128 + u * 16, ac + (long)r * KP2 + ldq * 8);
        }
        const int k0 = c * KC;
        const __half* brow = Bb + (long)(k0 + bro) * HWD + bn0;
#pragma unroll
        for (int i = 0; i < 4; i++) {
            int u = bu0 + 4 * i;
            cp16(sB + bro * 256 + ((u ^ (bro & 7)) * 16), brow + u * 8);
        }
        CP_COMMIT();
    };

    float acc[4][4][4] = {};

    const int l7 = l & 7;
    const int a_x = l >> 4;
    int arow[4];
#pragma unroll
    for (int mi = 0; mi < 4; mi++)
        arow[mi] = (wm * 64 + mi * 16 + (l & 15)) * 128;
    const int b_row_l = l & 15;
    const int b_u_l   = wn * 4 + (l >> 4);

    load_chunk(0, 0);
    load_chunk(1, 1);

    for (int c = 0; c < NCHUNK2; c++) {
        if (c + 2 < NCHUNK2) {
            asm volatile("cp.async.wait_group 1;" ::: "memory");
        } else {
            asm volatile("cp.async.wait_group 0;" ::: "memory");
        }
        __syncthreads();
        if (c + 2 < NCHUNK2) load_chunk(c + 2, (c + 2) % NSTAGE);

        const int s = c % NSTAGE;
        const uint32_t sA = smBase + s * STAGE;
        const uint32_t sB = sA + ATILE;

#pragma unroll
        for (int kk = 0; kk < 4; kk++) {
            uint32_t afr[4][4];
#pragma unroll
            for (int mi = 0; mi < 4; mi++) {
                uint32_t u = (uint32_t)((kk * 2 + a_x) ^ l7);
                ldmx4(afr[mi], sA + arow[mi] + u * 16);
            }
            uint32_t bfr[4][2];
#pragma unroll
            for (int g = 0; g < 2; g++) {
                uint32_t t4[4];
                int row = kk * 16 + b_row_l;
                int u = b_u_l + g * 2;
                ldmx4t(t4, sB + row * 256 + ((u ^ (row & 7)) * 16));
                bfr[2 * g][0] = t4[0]; bfr[2 * g][1] = t4[1];
                bfr[2 * g + 1][0] = t4[2]; bfr[2 * g + 1][1] = t4[3];
            }
#pragma unroll
            for (int mi = 0; mi < 4; mi++)
#pragma unroll
                for (int ni = 0; ni < 4; ni++)
                    mma16816h(acc[mi][ni], afr[mi], bfr[ni]);
        }
        __syncthreads();
    }

    const int crow = l >> 2, ccol = (l & 3) * 2;
#pragma unroll
    for (int mi = 0; mi < 4; mi++) {
#pragma unroll
        for (int ni = 0; ni < 4; ni++) {
            float* p = Cb + (long)(wm * 64 + mi * 16 + crow) * HWD + wn * 32 + ni * 8 + ccol;
            *(float2*)p = make_float2(acc[mi][ni][0], acc[mi][ni][1]);
            *(float2*)(p + 8L * HWD) = make_float2(acc[mi][ni][2], acc[mi][ni][3]);
        }
    }
}

// ---------------------------------------------------------------------------
// Split qkv_w -> A' [1152][1152] bf16 = [hi | lo | hi]
// ---------------------------------------------------------------------------
__global__ void split_w(const float* __restrict__ w, __nv_bfloat16* __restrict__ o)
{
    int idx = blockIdx.x * 256 + threadIdx.x;
    if (idx >= C3 * DIM) return;
    int m = idx / DIM, k = idx % DIM;
    float v = w[idx];
    __nv_bfloat16 hi = __float2bfloat16(v);
    __nv_bfloat16 lo = __float2bfloat16(v - __bfloat162float(hi));
    o[(long)m * KP + k]       = hi;
    o[(long)m * KP + 384 + k] = lo;
    o[(long)m * KP + 768 + k] = hi;
}

// ---------------------------------------------------------------------------
// split_c: fp32 [b][384][HWD] -> hi/lo bf16 planes, same layout
// ---------------------------------------------------------------------------
__global__ void __launch_bounds__(256)
split_c(const float* __restrict__ src, __nv_bfloat16* __restrict__ hi,
        __nv_bfloat16* __restrict__ lo)
{
    long i4 = (long)blockIdx.x * 256 + threadIdx.x;   // float4 index
    float4 v = ((const float4*)src)[i4];
    __nv_bfloat16 hx = __float2bfloat16(v.x);
    __nv_bfloat16 hy = __float2bfloat16(v.y);
    __nv_bfloat16 hz = __float2bfloat16(v.z);
    __nv_bfloat16 hw = __float2bfloat16(v.w);
    __nv_bfloat162 h01, h23, l01, l23;
    h01.x = hx; h01.y = hy; h23.x = hz; h23.y = hw;
    l01.x = __float2bfloat16(v.x - __bfloat162float(hx));
    l01.y = __float2bfloat16(v.y - __bfloat162float(hy));
    l23.x = __float2bfloat16(v.z - __bfloat162float(hz));
    l23.y = __float2bfloat16(v.w - __bfloat162float(hw));
    ((__nv_bfloat162*)hi)[i4 * 2]     = h01;
    ((__nv_bfloat162*)hi)[i4 * 2 + 1] = h23;
    ((__nv_bfloat162*)lo)[i4 * 2]     = l01;
    ((__nv_bfloat162*)lo)[i4 * 2 + 1] = l23;
}

// ---------------------------------------------------------------------------
// Depthwise 3x3: q/k -> fp32 + norms, v -> single fp16 plane
// ---------------------------------------------------------------------------
__global__ void __launch_bounds__(256)
dwconv3(const float* __restrict__ in, const float* __restrict__ w,
        float* __restrict__ out, float* __restrict__ ssp,
        __half* __restrict__ vh)
{
    __shared__ float pl[(SROWS + 2) * SPITCH];
    __shared__ float red[256];

    const int strip = blockIdx.x & (NSTRIP - 1);
    const int c = (blockIdx.x >> 2) % C3;
    const int b = blockIdx.x / (NSTRIP * C3);
    const int tid = threadIdx.x;

#pragma unroll
    for (int i = tid; i < (SROWS + 2) * SPITCH; i += 256)
        pl[i] = 0.f;
    __syncthreads();

    const int r0 = strip * SROWS;
    const float* ip = in + ((long)b * C3 + c) * HWD;

    {
        const int rlo = (strip == 0) ? 1 : 0;
        const int rhi = (strip == NSTRIP - 1) ? SROWS : SROWS + 1;
        const int njobs = (rhi - rlo + 1) * 32;
        for (int i = tid; i < njobs; i += 256) {
            int lr = rlo + (i >> 5);
            int x4 = (i & 31) * 4;
            *(float4*)&pl[lr * SPITCH + 4 + x4] =
                *(const float4*)&ip[(long)(r0 - 1 + lr) * 128 + x4];
        }
    }

    const float* wp = w + c * 9;
    float w0 = wp[0], w1 = wp[1], w2 = wp[2];
    float w3 = wp[3], w4 = wp[4], w5 = wp[5];
    float w6 = wp[6], w7 = wp[7], w8 = wp[8];
    __syncthreads();

    const int tx = tid & 31, ty = tid >> 5;
    const int x4 = tx * 4;
    const int h0 = ty * 4;

    float4 Ar[3], Br[3], Cr[3];
    auto loadrow = [&](int srow, int slot) {
        int idx = srow * SPITCH + 4 + x4;
        Ar[slot] = *(float4*)&pl[idx - 4];
        Br[slot] = *(float4*)&pl[idx];
        Cr[slot] = *(float4*)&pl[idx + 4];
    };
    loadrow(h0 + 0, 0);
    loadrow(h0 + 1, 1);
    loadrow(h0 + 2, 2);

    const bool isV = (c >= 768);
    float4* op4 = (float4*)(out + ((long)b * C3 + c) * HWD + (long)r0 * 128);
    __half2* vh2 = nullptr;
    if (isV) {
        long off = ((long)b * DIM + (c - 768)) * HWD + (long)r0 * 128;
        vh2 = (__half2*)(vh + off);
    }
    float ss = 0.f;

#pragma unroll
    for (int i = 0; i < 4; i++) {
        const int s0 = i % 3, s1 = (i + 1) % 3, s2 = (i + 2) % 3;
        float4 s;
        s.x = w0 * Ar[s0].w + w1 * Br[s0].x + w2 * Br[s0].y
            + w3 * Ar[s1].w + w4 * Br[s1].x + w5 * Br[s1].y
            + w6 * Ar[s2].w + w7 * Br[s2].x + w8 * Br[s2].y;
        s.y = w0 * Br[s0].x + w1 * Br[s0].y + w2 * Br[s0].z
            + w3 * Br[s1].x + w4 * Br[s1].y + w5 * Br[s1].z
            + w6 * Br[s2].x + w7 * Br[s2].y + w8 * Br[s2].z;
        s.z = w0 * Br[s0].y + w1 * Br[s0].z + w2 * Br[s0].w
            + w3 * Br[s1].y + w4 * Br[s1].z + w5 * Br[s1].w
            + w6 * Br[s2].y + w7 * Br[s2].z + w8 * Br[s2].w;
        s.w = w0 * Br[s0].z + w1 * Br[s0].w + w2 * Cr[s0].x
            + w3 * Br[s1].z + w4 * Br[s1].w + w5 * Cr[s1].x
            + w6 * Br[s2].z + w7 * Br[s2].w + w8 * Cr[s2].x;
        if (isV) {
            int e2 = (h0 + i) * 64 + tx * 2;
            vh2[e2]     = __floats2half2_rn(s.x, s.y);
            vh2[e2 + 1] = __floats2half2_rn(s.z, s.w);
        } else {
            op4[(h0 + i) * 32 + tx] = s;
            ss += s.x * s.x + s.y * s.y + s.z * s.z + s.w * s.w;
        }
        if (i < 3) loadrow(h0 + 3 + i, s0);
    }

    if (c < 768) {
        red[tid] = ss;
        __syncthreads();
        for (int st = 128; st > 0; st >>= 1) {
            if (tid < st) red[tid] += red[tid + st];
            __syncthreads();
        }
        if (tid == 0)
            ssp[(b * 768 + c) * NSTRIP + strip] = red[0];
    }
}

// finalize inv norms from strip partials
__global__ void norm_fin(const float* __restrict__ ssp, float* __restrict__ inv)
{
    int i = blockIdx.x * 256 + threadIdx.x;
    if (i >= BATCH * 768) return;
    float s = 0.f;
#pragma unroll
    for (int j = 0; j < NSTRIP; j++) s += ssp[i * NSTRIP + j];
    inv[i] = 1.f / fmaxf(sqrtf(s), 1e-12f);
}

// ---------------------------------------------------------------------------
// Gram partial (unchanged)
// ---------------------------------------------------------------------------
__global__ void __launch_bounds__(256)
gram_partial(const float* __restrict__ qkv2, float* __restrict__ gpart)
{
    const int chunk = blockIdx.x;
    const int bh = blockIdx.y;
    const int b = bh >> 3, h = bh & 7;
    const float* qb = qkv2 + ((long)b * C3 + h * CH) * HWD;
    const float* kb = qb + (long)DIM * HWD;

    __shared__ float qs[64][49], ks[64][49];
    const int tid = threadIdx.x;
    const int tx = tid & 15, ty = tid >> 4;
    float acc[3][3] = {};

    const int n0 = chunk * 512;
    for (int slab = 0; slab < 8; slab++) {
        const int base = n0 + slab * 64;
        __syncthreads();
#pragma unroll
        for (int j = 0; j < 3; j++) {
            int id = tid + j * 256;
            int rid = id >> 4, c4 = id & 15;
            float4 v = *(const float4*)(qb + (long)rid * HWD + base + c4 * 4);
            qs[c4 * 4 + 0][rid] = v.x; qs[c4 * 4 + 1][rid] = v.y;
            qs[c4 * 4 + 2][rid] = v.z; qs[c4 * 4 + 3][rid] = v.w;
            float4 u = *(const float4*)(kb + (long)rid * HWD + base + c4 * 4);
            ks[c4 * 4 + 0][rid] = u.x; ks[c4 * 4 + 1][rid] = u.y;
            ks[c4 * 4 + 2][rid] = u.z; ks[c4 * 4 + 3][rid] = u.w;
        }
        __syncthreads();
#pragma unroll 8
        for (int t = 0; t < 64; t++) {
            float qa[3], ka[3];
#pragma unroll
            for (int i = 0; i < 3; i++) qa[i] = qs[t][ty * 3 + i];
#pragma unroll
            for (int j = 0; j < 3; j++) ka[j] = ks[t][tx * 3 + j];
#pragma unroll
            for (int i = 0; i < 3; i++)
#pragma unroll
                for (int j = 0; j < 3; j++)
                    acc[i][j] += qa[i] * ka[j];
        }
    }
    float* op = gpart + ((long)chunk * 64 + bh) * (CH * CH);
#pragma unroll
    for (int i = 0; i < 3; i++)
#pragma unroll
        for (int j = 0; j < 3; j++)
            op[(ty * 3 + i) * CH + tx * 3 + j] = acc[i][j];
}

__global__ void gram_scale(const float* __restrict__ gpart, const float* __restrict__ inv,
                           const float* __restrict__ temp, float* __restrict__ attn)
{
    int idx = blockIdx.x * 256 + threadIdx.x;
    if (idx >= 64 * CH * CH) return;
    int bh = idx / (CH * CH), r = idx % (CH * CH);
    int c = r / CH, d = r % CH;
    int b = bh >> 3, h = bh & 7;
    float s = 0.f;
#pragma unroll
    for (int ck = 0; ck < GCH; ck++) s += gpart[((long)ck * 64 + bh) * (CH * CH) + r];
    float iq = inv[b * 768 + h * CH + c];
    float ik = inv[b * 768 + 384 + h * CH + d];
    attn[idx] = s * iq * ik * temp[h];
}

__global__ void topk_softmax(float* __restrict__ attn)
{
    int row = blockIdx.x;
    float* p = attn + (long)row * CH;
    __shared__ float s[CH], e[CH];
    int i = threadIdx.x;
    if (i < CH) s[i] = p[i];
    __syncthreads();
    if (i < CH) {
        float v = s[i];
        int cnt = 0;
        float m = -1e30f;
#pragma unroll
        for (int j = 0; j < CH; j++) {
            cnt += (s[j] > v);
            m = fmaxf(m, s[j]);
        }
        e[i] = (cnt < TOPKN) ? expf(v - m) : 0.f;
    }
    __syncthreads();
    if (i < CH) {
        float sum = 0.f;
#pragma unroll
        for (int j = 0; j < CH; j++) sum += e[j];
        p[i] = e[i] / sum;
    }
}

// ---------------------------------------------------------------------------
// Fold proj_w @ blockdiag(attn) -> Wf fp16 [b][o][384] (single plane)
// ---------------------------------------------------------------------------
__global__ void fold_proj(const float* __restrict__ projw, const float* __restrict__ attn,
                          __half* __restrict__ Wf)
{
    int idx = blockIdx.x * 256 + threadIdx.x;
    if (idx >= BATCH * DIM * DIM) return;
    int b = idx / (DIM * DIM);
    int r = idx % (DIM * DIM);
    int o = r / DIM, dg = r % DIM;
    int h = dg / CH, d = dg % CH;
    const float* pw = projw + o * DIM + h * CH;
    const float* at = attn + ((long)(b * NH + h) * CH) * CH + d;
    float s = 0.f;
#pragma unroll
    for (int c = 0; c < CH; c++) s += pw[c] * at[c * CH];
    Wf[((long)b * DIM + o) * KP2 + dg] = __float2half_rn(s);
}

// ---------------------------------------------------------------------------
extern "C" void kernel_launch(void* const* d_in, const int* in_sizes, int n_in,
                              void* d_out, int out_size)
{
    const float* x      = (const float*)d_in[0];
    const float* qkv_w  = (const float*)d_in[1];
    const float* dw_w   = (const float*)d_in[2];
    const float* proj_w = (const float*)d_in[3];
    const float* temp   = (const float*)d_in[4];
    float* out = (float*)d_out;

    float *qkv1, *qkv2, *ssp, *inv, *gpart, *attn;
    __nv_bfloat16 *A1, *xhi, *xlo;
    __half *vh, *Wf;
    cudaGetSymbolAddress((void**)&qkv1,  g_qkv1);
    cudaGetSymbolAddress((void**)&qkv2,  g_qkv2);
    cudaGetSymbolAddress((void**)&ssp,   g_ssp);
    cudaGetSymbolAddress((void**)&inv,   g_inv);
    cudaGetSymbolAddress((void**)&gpart, g_gpart);
    cudaGetSymbolAddress((void**)&attn,  g_attn);
    cudaGetSymbolAddress((void**)&A1,    g_A1);
    cudaGetSymbolAddress((void**)&xhi,   g_xhi);
    cudaGetSymbolAddress((void**)&xlo,   g_xlo);
    cudaGetSymbolAddress((void**)&vh,    g_vh);
    cudaGetSymbolAddress((void**)&Wf,    g_Wf);

    cudaFuncSetAttribute(gemm_split, cudaFuncAttributeMaxDynamicSharedMemorySize, GEMM_SMEM);
    cudaFuncSetAttribute(gemm2_f16, cudaFuncAttributeMaxDynamicSharedMemorySize, GEMM_SMEM);

    // 0) operand prep (no transposes)
    split_w<<<(C3 * DIM + 255) / 256, 256>>>(qkv_w, A1);
    split_c<<<(int)(((long)BATCH * DIM * HWD / 4) / 256), 256>>>(x, xhi, xlo);

    // 1) qkv = qkv_w @ x   (bf16 3-term, protects top-k)
    gemm_split<<<dim3(C3 / BM, HWD / BN, BATCH), 256, GEMM_SMEM>>>(
        A1, 0L, xhi, xlo, qkv1, (long)C3 * HWD);

    // 2) depthwise 3x3: q/k -> fp32 + norms, v -> fp16 plane
    dwconv3<<<BATCH * C3 * NSTRIP, 256>>>(qkv1, dw_w, qkv2, ssp, vh);
    norm_fin<<<(BATCH * 768 + 255) / 256, 256>>>(ssp, inv);

    // 3) Gram + scale + topk softmax
    gram_partial<<<dim3(GCH, BATCH * NH), 256>>>(qkv2, gpart);
    gram_scale<<<(64 * CH * CH + 255) / 256, 256>>>(gpart, inv, temp, attn);
    topk_softmax<<<BATCH * NH * CH, 64>>>(attn);

    // 4) fold proj @ blockdiag(attn) -> fp16 single plane
    fold_proj<<<(BATCH * DIM * DIM + 255) / 256, 256>>>(proj_w, attn, Wf);

    // 5) out = Wh @ vh   (fp16, 6 chunks)
    gemm2_f16<<<dim3(DIM / BM, HWD / BN, BATCH), 256, GEMM_SMEM>>>(
        Wf, (long)DIM * KP2, vh, out, (long)DIM * HWD);
}